// round 6
// baseline (speedup 1.0000x reference)
#include <cuda_runtime.h>
#include <mma.h>
using namespace nvcuda;

// Problem shape (fixed per dataset)
#define MAXN 50000
#define MAXE 800000
#define HH   128
#define GG   64
#define OO   64
#define NPAD (MAXN + 128)

// ---------------- scratch (static device globals; no allocs) ----------------
__device__ __align__(128) float    g_h   [MAXN * HH];
__device__ __align__(128) float    g_hp  [MAXN * HH];
__device__ __align__(128) float    g_ahi [NPAD * HH];
__device__ __align__(128) float    g_alo [NPAD * HH];
__device__ __align__(128) float    g_whi [4 * HH * HH];
__device__ __align__(128) float    g_wlo [4 * HH * HH];
__device__ __align__(128) float    g_asp [4 * MAXN];   // as(b0), as(b1), ad(b0), ad(b1)
__device__ __align__(128) float    g_asum[2 * MAXN];   // combined as, ad
__device__ __align__(128) float    g_ev  [MAXE + MAXN];// per-edge leaky score
__device__ __align__(128) float    g_pool[GG * HH];
// CSR scratch
__device__ __align__(128) int g_counts[MAXN];
__device__ __align__(128) int g_part  [MAXN];
__device__ __align__(128) int g_rowptr[MAXN + 1];
__device__ __align__(128) int g_fillp [MAXN];
__device__ __align__(128) int g_bsum  [256];
__device__ __align__(128) int g_col   [MAXE + MAXN];
__device__ int g_is64;

// ---------------- helpers ----------------
__device__ __forceinline__ int ld_idx(const void* p, long i, int is64) {
    if (is64) return (int)((const long long*)p)[i];
    return ((const int*)p)[i];
}
__device__ __forceinline__ float tf32r(float x) {
    unsigned u;
    asm("cvt.rna.tf32.f32 %0, %1;" : "=r"(u) : "f"(x));
    return __uint_as_float(u);
}

// ---------------- kernels ----------------

__global__ void k_detect(const unsigned long long* ei) {
    if (threadIdx.x == 0 && blockIdx.x == 0) {
        int is64 = 1;
        for (int i = 0; i < 64; i++)
            if (ei[i] > 1000000ull) is64 = 0;
        g_is64 = is64;
    }
}

__global__ void k_zero_i(int* p, int n) {
    int i = blockIdx.x * blockDim.x + threadIdx.x;
    if (i < n) p[i] = 0;
}
__global__ void k_zero(float4* p, int n4) {
    int i = blockIdx.x * blockDim.x + threadIdx.x;
    if (i < n4) p[i] = make_float4(0.f, 0.f, 0.f, 0.f);
}

// split W0 + all Wl layers into tf32 hi/lo (once)
__global__ void k_splitW(const float* __restrict__ W0, const float* __restrict__ Wl,
                         float* __restrict__ whi, float* __restrict__ wlo, int L) {
    int i = blockIdx.x * blockDim.x + threadIdx.x;
    int total = (L + 1) * HH * HH;
    if (i >= total) return;
    float v = (i < HH * HH) ? W0[i] : Wl[i - HH * HH];
    float h = tf32r(v);
    whi[i] = h;
    wlo[i] = tf32r(v - h);
}

// split A rows into tf32 hi/lo
__global__ void k_splitA(const float4* __restrict__ A, float4* __restrict__ hi4,
                         float4* __restrict__ lo4, int n4) {
    int i = blockIdx.x * blockDim.x + threadIdx.x;
    if (i >= n4) return;
    float4 a = A[i];
    float4 h, l;
    h.x = tf32r(a.x); l.x = tf32r(a.x - h.x);
    h.y = tf32r(a.y); l.y = tf32r(a.y - h.y);
    h.z = tf32r(a.z); l.z = tf32r(a.z - h.z);
    h.w = tf32r(a.w); l.w = tf32r(a.w - h.w);
    hi4[i] = h; lo4[i] = l;
}

// ---- CSR build (once per launch) ----
__global__ void k_hist(const void* ei, int* counts, int E, int n) {
    int e = blockIdx.x * blockDim.x + threadIdx.x;
    if (e >= E + n) return;
    int d = (e < E) ? ld_idx(ei, (long)E + e, g_is64) : (e - E);
    atomicAdd(&counts[d], 1);
}

__global__ __launch_bounds__(1024) void k_scanA(const int* counts, int* part,
                                                int* bsum, int n) {
    __shared__ int ws[32];
    int i = blockIdx.x * 1024 + threadIdx.x;
    int lane = threadIdx.x & 31, wid = threadIdx.x >> 5;
    int x = (i < n) ? counts[i] : 0;
#pragma unroll
    for (int o = 1; o < 32; o <<= 1) {
        int y = __shfl_up_sync(0xffffffffu, x, o);
        if (lane >= o) x += y;
    }
    if (lane == 31) ws[wid] = x;
    __syncthreads();
    if (wid == 0) {
        int y = ws[lane];
#pragma unroll
        for (int o = 1; o < 32; o <<= 1) {
            int z = __shfl_up_sync(0xffffffffu, y, o);
            if (lane >= o) y += z;
        }
        ws[lane] = y;
    }
    __syncthreads();
    int incl = x + (wid ? ws[wid - 1] : 0);
    if (i < n) part[i] = incl;
    if (threadIdx.x == 1023) bsum[blockIdx.x] = incl;
}

__global__ void k_scanC(const int* part, const int* bsum, const int* counts,
                        int* rowptr, int* fillp, int n) {
    __shared__ int pref;
    if (threadIdx.x == 0) {
        int target = blockIdx.x >> 2;
        int run = 0;
        for (int k = 0; k < target; k++) run += bsum[k];
        pref = run;
    }
    __syncthreads();
    int i = blockIdx.x * 256 + threadIdx.x;
    if (i == 0) rowptr[0] = 0;
    if (i < n) {
        int incl = part[i] + pref;
        rowptr[i + 1] = incl;
        fillp[i] = incl - counts[i];
    }
}
__global__ void k_fill(const void* ei, int* fillp, int* col, int E, int n) {
    int e = blockIdx.x * blockDim.x + threadIdx.x;
    if (e >= E + n) return;
    int is64 = g_is64;
    int s, d;
    if (e < E) { s = ld_idx(ei, e, is64); d = ld_idx(ei, (long)E + e, is64); }
    else       { s = d = e - E; }
    int pos = atomicAdd(&fillp[d], 1);
    col[pos] = s;
}

// tf32 split-compensated tensor-core GEMM: C[n,128] = A@W (+bias).
// D = Ah@Wh + Ah@Wl + Al@Wh  (error ~2^-22). Block tile 128x64, 8 warps,
// each warp 16 rows x 64 cols. Fused epilogue: bias + alpha partials.
__global__ __launch_bounds__(256) void k_gemm_tc(
    const float* __restrict__ Ahi, const float* __restrict__ Alo,
    const float* __restrict__ Whi, const float* __restrict__ Wlo,
    const float* __restrict__ bias,
    const float* __restrict__ a_s, const float* __restrict__ a_d,
    float* __restrict__ asp, float* __restrict__ C, int nrows) {
    __shared__ float sepi[128 * 72];
    int w = threadIdx.x >> 5;
    int row0 = blockIdx.x * 128;
    int col0 = blockIdx.y * 64;
    long wrow = row0 + w * 16;

    wmma::fragment<wmma::accumulator, 16, 16, 8, float> acc[4];
#pragma unroll
    for (int j = 0; j < 4; j++) wmma::fill_fragment(acc[j], 0.f);

    wmma::fragment<wmma::matrix_a, 16, 16, 8, wmma::precision::tf32, wmma::row_major> ah, al;
    wmma::fragment<wmma::matrix_b, 16, 16, 8, wmma::precision::tf32, wmma::row_major> bh, bl;

#pragma unroll 4
    for (int k = 0; k < HH; k += 8) {
        wmma::load_matrix_sync(ah, Ahi + wrow * HH + k, HH);
        wmma::load_matrix_sync(al, Alo + wrow * HH + k, HH);
#pragma unroll
        for (int j = 0; j < 4; j++) {
            wmma::load_matrix_sync(bh, Whi + k * HH + col0 + j * 16, HH);
            wmma::load_matrix_sync(bl, Wlo + k * HH + col0 + j * 16, HH);
            wmma::mma_sync(acc[j], ah, bh, acc[j]);
            wmma::mma_sync(acc[j], ah, bl, acc[j]);
            wmma::mma_sync(acc[j], al, bh, acc[j]);
        }
    }
#pragma unroll
    for (int j = 0; j < 4; j++)
        wmma::store_matrix_sync(&sepi[(w * 16) * 72 + j * 16], acc[j], 72,
                                wmma::mem_row_major);
    __syncthreads();

    // epilogue: 2 threads per row, 32 cols each
    int r = threadIdx.x >> 1;
    int ch = (threadIdx.x & 1) * 32;
    int row = row0 + r;
    const float* srow = &sepi[r * 72 + ch];
    float ps = 0.f, pd = 0.f;
    float4 ov[8];
#pragma unroll
    for (int q = 0; q < 8; q++) {
        float4 v = make_float4(srow[q * 4], srow[q * 4 + 1],
                               srow[q * 4 + 2], srow[q * 4 + 3]);
        int c = col0 + ch + q * 4;
        if (bias) {
            v.x += bias[c]; v.y += bias[c + 1]; v.z += bias[c + 2]; v.w += bias[c + 3];
        }
        if (a_s) {
            ps += v.x * a_s[c] + v.y * a_s[c + 1] + v.z * a_s[c + 2] + v.w * a_s[c + 3];
            pd += v.x * a_d[c] + v.y * a_d[c + 1] + v.z * a_d[c + 2] + v.w * a_d[c + 3];
        }
        ov[q] = v;
    }
    if (a_s) {   // full-warp convergent shfl (pair threads share the same row)
        ps += __shfl_xor_sync(0xffffffffu, ps, 1);
        pd += __shfl_xor_sync(0xffffffffu, pd, 1);
    }
    if (row < nrows) {
#pragma unroll
        for (int q = 0; q < 8; q++)
            *(float4*)&C[(long)row * HH + col0 + ch + q * 4] = ov[q];
        if (a_s && (threadIdx.x & 1) == 0) {
            asp[row + blockIdx.y * nrows]             = ps;
            asp[row + 2 * nrows + blockIdx.y * nrows] = pd;
        }
    }
}

// combine the two col-block partials: asum[i] = as, asum[i+n] = ad
__global__ void k_combine(const float* __restrict__ asp, float* __restrict__ asum,
                          int n) {
    int i = blockIdx.x * blockDim.x + threadIdx.x;
    if (i >= n) return;
    asum[i]     = asp[i] + asp[i + n];
    asum[i + n] = asp[i + 2 * n] + asp[i + 3 * n];
}

// warp per destination node. Pass 1: gather as[src], compute leaky score,
// store it to ev[] (contiguous), online max/denom. Pass 2: sequential ev read
// + hp gather, fused bias+relu.
__global__ __launch_bounds__(256) void k_aggregate(
    const int* __restrict__ rowptr, const int* __restrict__ col,
    const float* __restrict__ asum, float* __restrict__ ev,
    const float* __restrict__ hp, const float* __restrict__ bias,
    float* __restrict__ hout, int n, int relu) {
    int gid = blockIdx.x * blockDim.x + threadIdx.x;
    int w = gid >> 5, lane = gid & 31;
    if (w >= n) return;
    int beg = rowptr[w], end = rowptr[w + 1];
    float add = __ldg(&asum[w + n]);

    float m = -3.4e38f, den = 0.f;
    for (int j = beg + lane; j < end; j += 32) {
        float v = __ldg(&asum[__ldg(&col[j])]) + add;
        v = v >= 0.f ? v : 0.2f * v;
        ev[j] = v;
        if (v > m) { den = den * __expf(m - v) + 1.f; m = v; }
        else den += __expf(v - m);
    }
#pragma unroll
    for (int o = 16; o > 0; o >>= 1) {
        float mo = __shfl_xor_sync(0xffffffffu, m, o);
        float dd = __shfl_xor_sync(0xffffffffu, den, o);
        float M = fmaxf(m, mo);
        den = den * __expf(m - M) + dd * __expf(mo - M);
        m = M;
    }
    float inv = 1.f / den;

    float4 acc = make_float4(0.f, 0.f, 0.f, 0.f);
    int j = beg;
#pragma unroll 1
    for (; j + 4 <= end; j += 4) {
        int   s0 = __ldg(&col[j]),     s1 = __ldg(&col[j + 1]);
        int   s2 = __ldg(&col[j + 2]), s3 = __ldg(&col[j + 3]);
        float a0 = __expf(ev[j]     - m) * inv;
        float a1 = __expf(ev[j + 1] - m) * inv;
        float a2 = __expf(ev[j + 2] - m) * inv;
        float a3 = __expf(ev[j + 3] - m) * inv;
        float4 h0 = __ldg(&((const float4*)hp)[(long)s0 * 32 + lane]);
        float4 h1 = __ldg(&((const float4*)hp)[(long)s1 * 32 + lane]);
        float4 h2 = __ldg(&((const float4*)hp)[(long)s2 * 32 + lane]);
        float4 h3 = __ldg(&((const float4*)hp)[(long)s3 * 32 + lane]);
        acc.x = fmaf(a0, h0.x, acc.x); acc.y = fmaf(a0, h0.y, acc.y);
        acc.z = fmaf(a0, h0.z, acc.z); acc.w = fmaf(a0, h0.w, acc.w);
        acc.x = fmaf(a1, h1.x, acc.x); acc.y = fmaf(a1, h1.y, acc.y);
        acc.z = fmaf(a1, h1.z, acc.z); acc.w = fmaf(a1, h1.w, acc.w);
        acc.x = fmaf(a2, h2.x, acc.x); acc.y = fmaf(a2, h2.y, acc.y);
        acc.z = fmaf(a2, h2.z, acc.z); acc.w = fmaf(a2, h2.w, acc.w);
        acc.x = fmaf(a3, h3.x, acc.x); acc.y = fmaf(a3, h3.y, acc.y);
        acc.z = fmaf(a3, h3.z, acc.z); acc.w = fmaf(a3, h3.w, acc.w);
    }
    for (; j < end; j++) {
        int   s0 = __ldg(&col[j]);
        float a0 = __expf(ev[j] - m) * inv;
        float4 h0 = __ldg(&((const float4*)hp)[(long)s0 * 32 + lane]);
        acc.x = fmaf(a0, h0.x, acc.x); acc.y = fmaf(a0, h0.y, acc.y);
        acc.z = fmaf(a0, h0.z, acc.z); acc.w = fmaf(a0, h0.w, acc.w);
    }
    float4 bb = ((const float4*)bias)[lane];
    acc.x += bb.x; acc.y += bb.y; acc.z += bb.z; acc.w += bb.w;
    if (relu) {
        acc.x = fmaxf(acc.x, 0.f); acc.y = fmaxf(acc.y, 0.f);
        acc.z = fmaxf(acc.z, 0.f); acc.w = fmaxf(acc.w, 0.f);
    }
    ((float4*)hout)[(long)w * 32 + lane] = acc;
}

// global_add_pool over sorted batch
__global__ void k_pool(const float* __restrict__ h, const void* batch,
                       float* __restrict__ pool, int n) {
    __shared__ float s[GG * HH];
    for (int i = threadIdx.x; i < GG * HH; i += 256) s[i] = 0.f;
    __syncthreads();
    int is64 = g_is64;
    int per = (n + gridDim.x - 1) / gridDim.x;
    int i0 = blockIdx.x * per;
    int i1 = min(n, i0 + per);
    int c = threadIdx.x & 127, sub = threadIdx.x >> 7;
    float accv = 0.f; int curg = -1;
    for (int r = i0 + sub; r < i1; r += 2) {
        int g = ld_idx(batch, r, is64);
        if (g != curg) {
            if (curg >= 0) atomicAdd(&s[curg * HH + c], accv);
            accv = 0.f; curg = g;
        }
        accv += h[(long)r * HH + c];
    }
    if (curg >= 0) atomicAdd(&s[curg * HH + c], accv);
    __syncthreads();
    for (int i = threadIdx.x; i < GG * HH; i += 256) {
        float v = s[i];
        if (v != 0.f) atomicAdd(&pool[i], v);
    }
}

__global__ void k_final(const float* __restrict__ pool, const float* __restrict__ Wf,
                        const float* __restrict__ bf, float* __restrict__ out) {
    int i = blockIdx.x * blockDim.x + threadIdx.x;
    if (i >= GG * OO) return;
    int g = i >> 6, o = i & 63;
    float sa = bf[o];
#pragma unroll 8
    for (int k = 0; k < HH; k++) sa += pool[g * HH + k] * Wf[k * OO + o];
    out[i] = sa;
}

// ---------------- launch ----------------
extern "C" void kernel_launch(void* const* d_in, const int* in_sizes, int n_in,
                              void* d_out, int out_size) {
    const float* x     = (const float*)d_in[0];
    const void*  ei    = d_in[1];
    const void*  batch = d_in[2];
    const float* W0    = (const float*)d_in[3];
    const float* b0    = (const float*)d_in[4];
    const float* Wl    = (const float*)d_in[5];
    const float* a_src = (const float*)d_in[6];
    const float* a_dst = (const float*)d_in[7];
    const float* bl    = (const float*)d_in[8];
    const float* Wf    = (const float*)d_in[9];
    const float* bf    = (const float*)d_in[10];
    float* out = (float*)d_out;

    int n  = in_sizes[0] / HH;
    int E  = in_sizes[1] / 2;
    int et = E + n;
    int L  = in_sizes[5] / (HH * HH);

    float *h, *hp, *ahi, *alo, *whi, *wlo, *asp, *asum, *ev, *pool;
    int *counts, *part, *rowptr, *fillp, *bsum, *col;
    cudaGetSymbolAddress((void**)&h,    g_h);
    cudaGetSymbolAddress((void**)&hp,   g_hp);
    cudaGetSymbolAddress((void**)&ahi,  g_ahi);
    cudaGetSymbolAddress((void**)&alo,  g_alo);
    cudaGetSymbolAddress((void**)&whi,  g_whi);
    cudaGetSymbolAddress((void**)&wlo,  g_wlo);
    cudaGetSymbolAddress((void**)&asp,  g_asp);
    cudaGetSymbolAddress((void**)&asum, g_asum);
    cudaGetSymbolAddress((void**)&ev,   g_ev);
    cudaGetSymbolAddress((void**)&pool, g_pool);
    cudaGetSymbolAddress((void**)&counts, g_counts);
    cudaGetSymbolAddress((void**)&part,   g_part);
    cudaGetSymbolAddress((void**)&rowptr, g_rowptr);
    cudaGetSymbolAddress((void**)&fillp,  g_fillp);
    cudaGetSymbolAddress((void**)&bsum,   g_bsum);
    cudaGetSymbolAddress((void**)&col,    g_col);

    dim3 tg((n + 127) / 128, 2);
    int nb = (n + 1023) / 1024;
    int n4 = n * 32;

    // slots 1-3 (slot 4 = k_gemm_tc profiled by ncu -s 5 -c 1)
    k_splitW<<<((L + 1) * HH * HH + 255) / 256, 256>>>(W0, Wl, whi, wlo, L);
    k_splitA<<<(n4 + 255) / 256, 256>>>((const float4*)x, (float4*)ahi, (float4*)alo, n4);
    k_detect<<<1, 32>>>((const unsigned long long*)ei);

    // slot 4: h = x @ W0 + b0
    k_gemm_tc<<<tg, 256>>>(ahi, alo, whi, wlo, b0, nullptr, nullptr, nullptr, h, n);

    // CSR build
    k_zero_i<<<(n + 255) / 256, 256>>>(counts, n);
    k_hist<<<(et + 255) / 256, 256>>>(ei, counts, E, n);
    k_scanA<<<nb, 1024>>>(counts, part, bsum, n);
    k_scanC<<<(n + 255) / 256, 256>>>(part, bsum, counts, rowptr, fillp, n);
    k_fill<<<(et + 255) / 256, 256>>>(ei, fillp, col, E, n);

    for (int l = 0; l < L; l++) {
        k_splitA<<<(n4 + 255) / 256, 256>>>((const float4*)h, (float4*)ahi, (float4*)alo, n4);
        k_gemm_tc<<<tg, 256>>>(ahi, alo, whi + (long)(l + 1) * HH * HH,
                               wlo + (long)(l + 1) * HH * HH, nullptr,
                               a_src + l * HH, a_dst + l * HH, asp, hp, n);
        k_combine<<<(n + 255) / 256, 256>>>(asp, asum, n);
        k_aggregate<<<(n * 32 + 255) / 256, 256>>>(rowptr, col, asum, ev, hp,
                                                   bl + l * HH, h, n,
                                                   (l < L - 1) ? 1 : 0);
    }

    k_zero<<<(GG * HH / 4 + 255) / 256, 256>>>((float4*)pool, GG * HH / 4);
    k_pool<<<64, 256>>>(h, batch, pool, n);
    k_final<<<(GG * OO + 255) / 256, 256>>>(pool, Wf, bf, out);
}

// round 7
// speedup vs baseline: 1.0080x; 1.0080x over previous
#include <cuda_runtime.h>
#include <mma.h>
using namespace nvcuda;

// Problem shape (fixed per dataset)
#define MAXN 50000
#define MAXE 800000
#define HH   128
#define GG   64
#define OO   64

// ---------------- scratch (static device globals; no allocs) ----------------
__device__ __align__(128) float    g_h   [MAXN * HH];
__device__ __align__(128) float    g_hp  [MAXN * HH];
__device__ __align__(128) float    g_whi [4 * HH * HH];
__device__ __align__(128) float    g_wlo [4 * HH * HH];
__device__ __align__(128) float    g_asp [4 * MAXN];   // as(b0), as(b1), ad(b0), ad(b1)
__device__ __align__(128) float    g_asum[2 * MAXN];   // combined as, ad
__device__ __align__(128) float    g_ev  [MAXE + MAXN];// per-edge leaky score
__device__ __align__(128) float    g_pool[GG * HH];
// CSR scratch
__device__ __align__(128) int g_counts[MAXN];
__device__ __align__(128) int g_part  [MAXN];
__device__ __align__(128) int g_rowptr[MAXN + 1];
__device__ __align__(128) int g_fillp [MAXN];
__device__ __align__(128) int g_bsum  [256];
__device__ __align__(128) int g_col   [MAXE + MAXN];
__device__ int g_is64;

// ---------------- helpers ----------------
__device__ __forceinline__ int ld_idx(const void* p, long i, int is64) {
    if (is64) return (int)((const long long*)p)[i];
    return ((const int*)p)[i];
}
__device__ __forceinline__ float tf32r(float x) {
    unsigned u;
    asm("cvt.rna.tf32.f32 %0, %1;" : "=r"(u) : "f"(x));
    return __uint_as_float(u);
}

// ---------------- kernels ----------------

__global__ void k_detect(const unsigned long long* ei) {
    if (threadIdx.x == 0 && blockIdx.x == 0) {
        int is64 = 1;
        for (int i = 0; i < 64; i++)
            if (ei[i] > 1000000ull) is64 = 0;
        g_is64 = is64;
    }
}

__global__ void k_zero_i(int* p, int n) {
    int i = blockIdx.x * blockDim.x + threadIdx.x;
    if (i < n) p[i] = 0;
}
__global__ void k_zero(float4* p, int n4) {
    int i = blockIdx.x * blockDim.x + threadIdx.x;
    if (i < n4) p[i] = make_float4(0.f, 0.f, 0.f, 0.f);
}

// split W0 + all Wl layers into tf32 hi/lo (once)
__global__ void k_splitW(const float* __restrict__ W0, const float* __restrict__ Wl,
                         float* __restrict__ whi, float* __restrict__ wlo, int L) {
    int i = blockIdx.x * blockDim.x + threadIdx.x;
    int total = (L + 1) * HH * HH;
    if (i >= total) return;
    float v = (i < HH * HH) ? W0[i] : Wl[i - HH * HH];
    float h = tf32r(v);
    whi[i] = h;
    wlo[i] = tf32r(v - h);
}

// ---- CSR build (once per launch) ----
__global__ void k_hist(const void* ei, int* counts, int E, int n) {
    int e = blockIdx.x * blockDim.x + threadIdx.x;
    if (e >= E + n) return;
    int d = (e < E) ? ld_idx(ei, (long)E + e, g_is64) : (e - E);
    atomicAdd(&counts[d], 1);
}

__global__ __launch_bounds__(1024) void k_scanA(const int* counts, int* part,
                                                int* bsum, int n) {
    __shared__ int ws[32];
    int i = blockIdx.x * 1024 + threadIdx.x;
    int lane = threadIdx.x & 31, wid = threadIdx.x >> 5;
    int x = (i < n) ? counts[i] : 0;
#pragma unroll
    for (int o = 1; o < 32; o <<= 1) {
        int y = __shfl_up_sync(0xffffffffu, x, o);
        if (lane >= o) x += y;
    }
    if (lane == 31) ws[wid] = x;
    __syncthreads();
    if (wid == 0) {
        int y = ws[lane];
#pragma unroll
        for (int o = 1; o < 32; o <<= 1) {
            int z = __shfl_up_sync(0xffffffffu, y, o);
            if (lane >= o) y += z;
        }
        ws[lane] = y;
    }
    __syncthreads();
    int incl = x + (wid ? ws[wid - 1] : 0);
    if (i < n) part[i] = incl;
    if (threadIdx.x == 1023) bsum[blockIdx.x] = incl;
}

__global__ void k_scanC(const int* part, const int* bsum, const int* counts,
                        int* rowptr, int* fillp, int n) {
    __shared__ int pref;
    if (threadIdx.x == 0) {
        int target = blockIdx.x >> 2;
        int run = 0;
        for (int k = 0; k < target; k++) run += bsum[k];
        pref = run;
    }
    __syncthreads();
    int i = blockIdx.x * 256 + threadIdx.x;
    if (i == 0) rowptr[0] = 0;
    if (i < n) {
        int incl = part[i] + pref;
        rowptr[i + 1] = incl;
        fillp[i] = incl - counts[i];
    }
}
__global__ void k_fill(const void* ei, int* fillp, int* col, int E, int n) {
    int e = blockIdx.x * blockDim.x + threadIdx.x;
    if (e >= E + n) return;
    int is64 = g_is64;
    int s, d;
    if (e < E) { s = ld_idx(ei, e, is64); d = ld_idx(ei, (long)E + e, is64); }
    else       { s = d = e - E; }
    int pos = atomicAdd(&fillp[d], 1);
    col[pos] = s;
}

// tf32 split-compensated tensor-core GEMM with smem-staged tiles.
// C[n,128] = A@W (+bias).  D = Ah@Wh + Ah@Wl + Al@Wh.
// Block tile 128x64 (grid.y selects col half), K chunks of 64.
// Split (fp32 -> tf32 hi/lo) fused into the global->smem tile copy.
#define LDA 68   // smem leading dim (64 + 4 pad)
__global__ __launch_bounds__(256) void k_gemm_tc(
    const float* __restrict__ A,
    const float* __restrict__ Whi, const float* __restrict__ Wlo,
    const float* __restrict__ bias,
    const float* __restrict__ a_s, const float* __restrict__ a_d,
    float* __restrict__ asp, float* __restrict__ C, int nrows) {
    extern __shared__ float smem[];
    float* sAh = smem;                    // 128 x LDA
    float* sAl = sAh + 128 * LDA;         // 128 x LDA
    float* sWh = sAl + 128 * LDA;         // 64 x LDA
    float* sWl = sWh + 64 * LDA;          // 64 x LDA

    int t = threadIdx.x;
    int w = t >> 5;
    int row0 = blockIdx.x * 128;
    int col0 = blockIdx.y * 64;

    wmma::fragment<wmma::accumulator, 16, 16, 8, float> acc[4];
#pragma unroll
    for (int j = 0; j < 4; j++) wmma::fill_fragment(acc[j], 0.f);
    wmma::fragment<wmma::matrix_a, 16, 16, 8, wmma::precision::tf32, wmma::row_major> ah, al;
    wmma::fragment<wmma::matrix_b, 16, 16, 8, wmma::precision::tf32, wmma::row_major> bh, bl;

    for (int kc = 0; kc < HH; kc += 64) {
        // stage A chunk [128 x 64] with fused tf32 split (coalesced float4)
        for (int i = t; i < 128 * 16; i += 256) {
            int r = i >> 4, c4 = (i & 15) << 2;
            float4 a = make_float4(0.f, 0.f, 0.f, 0.f);
            if (row0 + r < nrows)
                a = *(const float4*)&A[(long)(row0 + r) * HH + kc + c4];
            float hx = tf32r(a.x), hy = tf32r(a.y), hz = tf32r(a.z), hw = tf32r(a.w);
            *(float4*)&sAh[r * LDA + c4] = make_float4(hx, hy, hz, hw);
            *(float4*)&sAl[r * LDA + c4] =
                make_float4(tf32r(a.x - hx), tf32r(a.y - hy),
                            tf32r(a.z - hz), tf32r(a.w - hw));
        }
        // stage W chunk [64 x 64] (already split in global)
        for (int i = t; i < 64 * 16; i += 256) {
            int r = i >> 4, c4 = (i & 15) << 2;
            *(float4*)&sWh[r * LDA + c4] =
                *(const float4*)&Whi[(long)(kc + r) * HH + col0 + c4];
            *(float4*)&sWl[r * LDA + c4] =
                *(const float4*)&Wlo[(long)(kc + r) * HH + col0 + c4];
        }
        __syncthreads();

#pragma unroll
        for (int kk = 0; kk < 64; kk += 8) {
            wmma::load_matrix_sync(ah, &sAh[(w * 16) * LDA + kk], LDA);
            wmma::load_matrix_sync(al, &sAl[(w * 16) * LDA + kk], LDA);
#pragma unroll
            for (int j = 0; j < 4; j++) {
                wmma::load_matrix_sync(bh, &sWh[kk * LDA + j * 16], LDA);
                wmma::load_matrix_sync(bl, &sWl[kk * LDA + j * 16], LDA);
                wmma::mma_sync(acc[j], ah, bh, acc[j]);
                wmma::mma_sync(acc[j], ah, bl, acc[j]);
                wmma::mma_sync(acc[j], al, bh, acc[j]);
            }
        }
        __syncthreads();
    }

    // epilogue via smem (reuse sAh region, stride LDA)
    float* sepi = sAh;
#pragma unroll
    for (int j = 0; j < 4; j++)
        wmma::store_matrix_sync(&sepi[(w * 16) * LDA + j * 16], acc[j], LDA,
                                wmma::mem_row_major);
    __syncthreads();

    int r = t >> 1;
    int ch = (t & 1) * 32;
    int row = row0 + r;
    const float* srow = &sepi[r * LDA + ch];
    float ps = 0.f, pd = 0.f;
    float4 ov[8];
#pragma unroll
    for (int q = 0; q < 8; q++) {
        float4 v = make_float4(srow[q * 4], srow[q * 4 + 1],
                               srow[q * 4 + 2], srow[q * 4 + 3]);
        int c = col0 + ch + q * 4;
        if (bias) {
            v.x += bias[c]; v.y += bias[c + 1]; v.z += bias[c + 2]; v.w += bias[c + 3];
        }
        if (a_s) {
            ps += v.x * a_s[c] + v.y * a_s[c + 1] + v.z * a_s[c + 2] + v.w * a_s[c + 3];
            pd += v.x * a_d[c] + v.y * a_d[c + 1] + v.z * a_d[c + 2] + v.w * a_d[c + 3];
        }
        ov[q] = v;
    }
    if (a_s) {
        ps += __shfl_xor_sync(0xffffffffu, ps, 1);
        pd += __shfl_xor_sync(0xffffffffu, pd, 1);
    }
    if (row < nrows) {
#pragma unroll
        for (int q = 0; q < 8; q++)
            *(float4*)&C[(long)row * HH + col0 + ch + q * 4] = ov[q];
        if (a_s && (t & 1) == 0) {
            asp[row + blockIdx.y * nrows]             = ps;
            asp[row + 2 * nrows + blockIdx.y * nrows] = pd;
        }
    }
}
#define GEMM_SMEM ((2 * 128 * LDA + 2 * 64 * LDA) * (int)sizeof(float))

// combine the two col-block partials: asum[i] = as, asum[i+n] = ad
__global__ void k_combine(const float* __restrict__ asp, float* __restrict__ asum,
                          int n) {
    int i = blockIdx.x * blockDim.x + threadIdx.x;
    if (i >= n) return;
    asum[i]     = asp[i] + asp[i + n];
    asum[i + n] = asp[i + 2 * n] + asp[i + 3 * n];
}

// warp per destination node; two-pass softmax with edge-score buffer.
__global__ __launch_bounds__(256) void k_aggregate(
    const int* __restrict__ rowptr, const int* __restrict__ col,
    const float* __restrict__ asum, float* __restrict__ ev,
    const float* __restrict__ hp, const float* __restrict__ bias,
    float* __restrict__ hout, int n, int relu) {
    int gid = blockIdx.x * blockDim.x + threadIdx.x;
    int w = gid >> 5, lane = gid & 31;
    if (w >= n) return;
    int beg = rowptr[w], end = rowptr[w + 1];
    float add = __ldg(&asum[w + n]);

    float m = -3.4e38f, den = 0.f;
    for (int j = beg + lane; j < end; j += 32) {
        float v = __ldg(&asum[__ldg(&col[j])]) + add;
        v = v >= 0.f ? v : 0.2f * v;
        ev[j] = v;
        if (v > m) { den = den * __expf(m - v) + 1.f; m = v; }
        else den += __expf(v - m);
    }
#pragma unroll
    for (int o = 16; o > 0; o >>= 1) {
        float mo = __shfl_xor_sync(0xffffffffu, m, o);
        float dd = __shfl_xor_sync(0xffffffffu, den, o);
        float M = fmaxf(m, mo);
        den = den * __expf(m - M) + dd * __expf(mo - M);
        m = M;
    }
    float inv = 1.f / den;

    float4 acc = make_float4(0.f, 0.f, 0.f, 0.f);
    int j = beg;
#pragma unroll 1
    for (; j + 4 <= end; j += 4) {
        int   s0 = __ldg(&col[j]),     s1 = __ldg(&col[j + 1]);
        int   s2 = __ldg(&col[j + 2]), s3 = __ldg(&col[j + 3]);
        float a0 = __expf(ev[j]     - m) * inv;
        float a1 = __expf(ev[j + 1] - m) * inv;
        float a2 = __expf(ev[j + 2] - m) * inv;
        float a3 = __expf(ev[j + 3] - m) * inv;
        float4 h0 = __ldg(&((const float4*)hp)[(long)s0 * 32 + lane]);
        float4 h1 = __ldg(&((const float4*)hp)[(long)s1 * 32 + lane]);
        float4 h2 = __ldg(&((const float4*)hp)[(long)s2 * 32 + lane]);
        float4 h3 = __ldg(&((const float4*)hp)[(long)s3 * 32 + lane]);
        acc.x = fmaf(a0, h0.x, acc.x); acc.y = fmaf(a0, h0.y, acc.y);
        acc.z = fmaf(a0, h0.z, acc.z); acc.w = fmaf(a0, h0.w, acc.w);
        acc.x = fmaf(a1, h1.x, acc.x); acc.y = fmaf(a1, h1.y, acc.y);
        acc.z = fmaf(a1, h1.z, acc.z); acc.w = fmaf(a1, h1.w, acc.w);
        acc.x = fmaf(a2, h2.x, acc.x); acc.y = fmaf(a2, h2.y, acc.y);
        acc.z = fmaf(a2, h2.z, acc.z); acc.w = fmaf(a2, h2.w, acc.w);
        acc.x = fmaf(a3, h3.x, acc.x); acc.y = fmaf(a3, h3.y, acc.y);
        acc.z = fmaf(a3, h3.z, acc.z); acc.w = fmaf(a3, h3.w, acc.w);
    }
    for (; j < end; j++) {
        int   s0 = __ldg(&col[j]);
        float a0 = __expf(ev[j] - m) * inv;
        float4 h0 = __ldg(&((const float4*)hp)[(long)s0 * 32 + lane]);
        acc.x = fmaf(a0, h0.x, acc.x); acc.y = fmaf(a0, h0.y, acc.y);
        acc.z = fmaf(a0, h0.z, acc.z); acc.w = fmaf(a0, h0.w, acc.w);
    }
    float4 bb = ((const float4*)bias)[lane];
    acc.x += bb.x; acc.y += bb.y; acc.z += bb.z; acc.w += bb.w;
    if (relu) {
        acc.x = fmaxf(acc.x, 0.f); acc.y = fmaxf(acc.y, 0.f);
        acc.z = fmaxf(acc.z, 0.f); acc.w = fmaxf(acc.w, 0.f);
    }
    ((float4*)hout)[(long)w * 32 + lane] = acc;
}

// global_add_pool over sorted batch
__global__ void k_pool(const float* __restrict__ h, const void* batch,
                       float* __restrict__ pool, int n) {
    __shared__ float s[GG * HH];
    for (int i = threadIdx.x; i < GG * HH; i += 256) s[i] = 0.f;
    __syncthreads();
    int is64 = g_is64;
    int per = (n + gridDim.x - 1) / gridDim.x;
    int i0 = blockIdx.x * per;
    int i1 = min(n, i0 + per);
    int c = threadIdx.x & 127, sub = threadIdx.x >> 7;
    float accv = 0.f; int curg = -1;
    for (int r = i0 + sub; r < i1; r += 2) {
        int g = ld_idx(batch, r, is64);
        if (g != curg) {
            if (curg >= 0) atomicAdd(&s[curg * HH + c], accv);
            accv = 0.f; curg = g;
        }
        accv += h[(long)r * HH + c];
    }
    if (curg >= 0) atomicAdd(&s[curg * HH + c], accv);
    __syncthreads();
    for (int i = threadIdx.x; i < GG * HH; i += 256) {
        float v = s[i];
        if (v != 0.f) atomicAdd(&pool[i], v);
    }
}

__global__ void k_final(const float* __restrict__ pool, const float* __restrict__ Wf,
                        const float* __restrict__ bf, float* __restrict__ out) {
    int i = blockIdx.x * blockDim.x + threadIdx.x;
    if (i >= GG * OO) return;
    int g = i >> 6, o = i & 63;
    float sa = bf[o];
#pragma unroll 8
    for (int k = 0; k < HH; k++) sa += pool[g * HH + k] * Wf[k * OO + o];
    out[i] = sa;
}

// ---------------- launch ----------------
extern "C" void kernel_launch(void* const* d_in, const int* in_sizes, int n_in,
                              void* d_out, int out_size) {
    const float* x     = (const float*)d_in[0];
    const void*  ei    = d_in[1];
    const void*  batch = d_in[2];
    const float* W0    = (const float*)d_in[3];
    const float* b0    = (const float*)d_in[4];
    const float* Wl    = (const float*)d_in[5];
    const float* a_src = (const float*)d_in[6];
    const float* a_dst = (const float*)d_in[7];
    const float* bl    = (const float*)d_in[8];
    const float* Wf    = (const float*)d_in[9];
    const float* bf    = (const float*)d_in[10];
    float* out = (float*)d_out;

    int n  = in_sizes[0] / HH;
    int E  = in_sizes[1] / 2;
    int et = E + n;
    int L  = in_sizes[5] / (HH * HH);

    float *h, *hp, *whi, *wlo, *asp, *asum, *ev, *pool;
    int *counts, *part, *rowptr, *fillp, *bsum, *col;
    cudaGetSymbolAddress((void**)&h,    g_h);
    cudaGetSymbolAddress((void**)&hp,   g_hp);
    cudaGetSymbolAddress((void**)&whi,  g_whi);
    cudaGetSymbolAddress((void**)&wlo,  g_wlo);
    cudaGetSymbolAddress((void**)&asp,  g_asp);
    cudaGetSymbolAddress((void**)&asum, g_asum);
    cudaGetSymbolAddress((void**)&ev,   g_ev);
    cudaGetSymbolAddress((void**)&pool, g_pool);
    cudaGetSymbolAddress((void**)&counts, g_counts);
    cudaGetSymbolAddress((void**)&part,   g_part);
    cudaGetSymbolAddress((void**)&rowptr, g_rowptr);
    cudaGetSymbolAddress((void**)&fillp,  g_fillp);
    cudaGetSymbolAddress((void**)&bsum,   g_bsum);
    cudaGetSymbolAddress((void**)&col,    g_col);

    cudaFuncSetAttribute(k_gemm_tc, cudaFuncAttributeMaxDynamicSharedMemorySize,
                         GEMM_SMEM);

    dim3 tg((n + 127) / 128, 2);
    int nb = (n + 1023) / 1024;

    // slots 1-3 (slot 4 = k_gemm_tc profiled by ncu -s 5 -c 1)
    k_splitW<<<((L + 1) * HH * HH + 255) / 256, 256>>>(W0, Wl, whi, wlo, L);
    k_detect<<<1, 32>>>((const unsigned long long*)ei);
    k_zero_i<<<(n + 255) / 256, 256>>>(counts, n);

    // slot 4: h = x @ W0 + b0
    k_gemm_tc<<<tg, 256, GEMM_SMEM>>>(x, whi, wlo, b0, nullptr, nullptr, nullptr, h, n);

    // CSR build
    k_hist<<<(et + 255) / 256, 256>>>(ei, counts, E, n);
    k_scanA<<<nb, 1024>>>(counts, part, bsum, n);
    k_scanC<<<(n + 255) / 256, 256>>>(part, bsum, counts, rowptr, fillp, n);
    k_fill<<<(et + 255) / 256, 256>>>(ei, fillp, col, E, n);

    for (int l = 0; l < L; l++) {
        k_gemm_tc<<<tg, 256, GEMM_SMEM>>>(h, whi + (long)(l + 1) * HH * HH,
                                          wlo + (long)(l + 1) * HH * HH, nullptr,
                                          a_src + l * HH, a_dst + l * HH,
                                          asp, hp, n);
        k_combine<<<(n + 255) / 256, 256>>>(asp, asum, n);
        k_aggregate<<<(n * 32 + 255) / 256, 256>>>(rowptr, col, asum, ev, hp,
                                                   bl + l * HH, h, n,
                                                   (l < L - 1) ? 1 : 0);
    }

    k_zero<<<(GG * HH / 4 + 255) / 256, 256>>>((float4*)pool, GG * HH / 4);
    k_pool<<<64, 256>>>(h, batch, pool, n);
    k_final<<<(GG * OO + 255) / 256, 256>>>(pool, Wf, bf, out);
}

// round 8
// speedup vs baseline: 1.5819x; 1.5694x over previous
#include <cuda_runtime.h>
#include <cuda_bf16.h>
#include <mma.h>
using namespace nvcuda;

// Problem shape (fixed per dataset)
#define MAXN 50000
#define MAXE 800000
#define HH   128
#define GG   64
#define OO   64

// ---------------- scratch (static device globals; no allocs) ----------------
__device__ __align__(128) float          g_h   [MAXN * HH];
__device__ __align__(128) float          g_hp  [MAXN * HH];
__device__ __align__(128) __nv_bfloat16  g_whi [4 * HH * HH];
__device__ __align__(128) __nv_bfloat16  g_wlo [4 * HH * HH];
__device__ __align__(128) float          g_asp [4 * MAXN];   // as(b0), as(b1), ad(b0), ad(b1)
__device__ __align__(128) float          g_asum[2 * MAXN];   // combined as, ad
__device__ __align__(128) float          g_ev  [MAXE + MAXN];// per-edge leaky score
__device__ __align__(128) float          g_pool[GG * HH];
// CSR scratch
__device__ __align__(128) int g_counts[MAXN];
__device__ __align__(128) int g_part  [MAXN];
__device__ __align__(128) int g_rowptr[MAXN + 1];
__device__ __align__(128) int g_fillp [MAXN];
__device__ __align__(128) int g_bsum  [256];
__device__ __align__(128) int g_col   [MAXE + MAXN];
__device__ int g_is64;

// ---------------- helpers ----------------
__device__ __forceinline__ int ld_idx(const void* p, long i, int is64) {
    if (is64) return (int)((const long long*)p)[i];
    return ((const int*)p)[i];
}

// ---------------- kernels ----------------

__global__ void k_detect(const unsigned long long* ei) {
    if (threadIdx.x == 0 && blockIdx.x == 0) {
        int is64 = 1;
        for (int i = 0; i < 64; i++)
            if (ei[i] > 1000000ull) is64 = 0;
        g_is64 = is64;
    }
}

__global__ void k_zero_i(int* p, int n) {
    int i = blockIdx.x * blockDim.x + threadIdx.x;
    if (i < n) p[i] = 0;
}
__global__ void k_zero(float4* p, int n4) {
    int i = blockIdx.x * blockDim.x + threadIdx.x;
    if (i < n4) p[i] = make_float4(0.f, 0.f, 0.f, 0.f);
}

// split W0 + all Wl layers into bf16 hi/lo (once)
__global__ void k_splitW(const float* __restrict__ W0, const float* __restrict__ Wl,
                         __nv_bfloat16* __restrict__ whi,
                         __nv_bfloat16* __restrict__ wlo, int L) {
    int i = blockIdx.x * blockDim.x + threadIdx.x;
    int total = (L + 1) * HH * HH;
    if (i >= total) return;
    float v = (i < HH * HH) ? W0[i] : Wl[i - HH * HH];
    __nv_bfloat16 h = __float2bfloat16(v);
    whi[i] = h;
    wlo[i] = __float2bfloat16(v - __bfloat162float(h));
}

// ---- CSR build (once per launch) ----
__global__ void k_hist(const void* ei, int* counts, int E, int n) {
    int e = blockIdx.x * blockDim.x + threadIdx.x;
    if (e >= E + n) return;
    int d = (e < E) ? ld_idx(ei, (long)E + e, g_is64) : (e - E);
    atomicAdd(&counts[d], 1);
}

__global__ __launch_bounds__(1024) void k_scanA(const int* counts, int* part,
                                                int* bsum, int n) {
    __shared__ int ws[32];
    int i = blockIdx.x * 1024 + threadIdx.x;
    int lane = threadIdx.x & 31, wid = threadIdx.x >> 5;
    int x = (i < n) ? counts[i] : 0;
#pragma unroll
    for (int o = 1; o < 32; o <<= 1) {
        int y = __shfl_up_sync(0xffffffffu, x, o);
        if (lane >= o) x += y;
    }
    if (lane == 31) ws[wid] = x;
    __syncthreads();
    if (wid == 0) {
        int y = ws[lane];
#pragma unroll
        for (int o = 1; o < 32; o <<= 1) {
            int z = __shfl_up_sync(0xffffffffu, y, o);
            if (lane >= o) y += z;
        }
        ws[lane] = y;
    }
    __syncthreads();
    int incl = x + (wid ? ws[wid - 1] : 0);
    if (i < n) part[i] = incl;
    if (threadIdx.x == 1023) bsum[blockIdx.x] = incl;
}

__global__ void k_scanC(const int* part, const int* bsum, const int* counts,
                        int* rowptr, int* fillp, int n) {
    __shared__ int pref;
    if (threadIdx.x == 0) {
        int target = blockIdx.x >> 2;
        int run = 0;
        for (int k = 0; k < target; k++) run += bsum[k];
        pref = run;
    }
    __syncthreads();
    int i = blockIdx.x * 256 + threadIdx.x;
    if (i == 0) rowptr[0] = 0;
    if (i < n) {
        int incl = part[i] + pref;
        rowptr[i + 1] = incl;
        fillp[i] = incl - counts[i];
    }
}
__global__ void k_fill(const void* ei, int* fillp, int* col, int E, int n) {
    int e = blockIdx.x * blockDim.x + threadIdx.x;
    if (e >= E + n) return;
    int is64 = g_is64;
    int s, d;
    if (e < E) { s = ld_idx(ei, e, is64); d = ld_idx(ei, (long)E + e, is64); }
    else       { s = d = e - E; }
    int pos = atomicAdd(&fillp[d], 1);
    col[pos] = s;
}

// bf16 split-compensated tensor-core GEMM with smem-staged tiles.
// C = A@W (+bias).  D = Ah@Wh + Ah@Wl + Al@Wh  (dropped lo*lo ~ 2^-16).
// Block tile 128x64 (grid.y = col half), K chunks of 64, 8 warps.
// smem ~54KB -> 3 blocks/SM.
#define BLD 72   // bf16 leading dim (64 + 8 pad)
#define GEMM_SMEM ((2 * 128 * BLD + 2 * 64 * BLD) * (int)sizeof(__nv_bfloat16))
__global__ __launch_bounds__(256, 3) void k_gemm_bf(
    const float* __restrict__ A,
    const __nv_bfloat16* __restrict__ Whi, const __nv_bfloat16* __restrict__ Wlo,
    const float* __restrict__ bias,
    const float* __restrict__ a_s, const float* __restrict__ a_d,
    float* __restrict__ asp, float* __restrict__ C, int nrows) {
    extern __shared__ __nv_bfloat16 smem[];
    __nv_bfloat16* sAh = smem;                 // 128 x BLD
    __nv_bfloat16* sAl = sAh + 128 * BLD;      // 128 x BLD
    __nv_bfloat16* sWh = sAl + 128 * BLD;      // 64 x BLD
    __nv_bfloat16* sWl = sWh + 64 * BLD;       // 64 x BLD

    int t = threadIdx.x;
    int w = t >> 5;
    int row0 = blockIdx.x * 128;
    int col0 = blockIdx.y * 64;

    wmma::fragment<wmma::accumulator, 16, 16, 16, float> acc[4];
#pragma unroll
    for (int j = 0; j < 4; j++) wmma::fill_fragment(acc[j], 0.f);
    wmma::fragment<wmma::matrix_a, 16, 16, 16, __nv_bfloat16, wmma::row_major> ah, al;
    wmma::fragment<wmma::matrix_b, 16, 16, 16, __nv_bfloat16, wmma::row_major> bh, bl;

    for (int kc = 0; kc < HH; kc += 64) {
        // stage A chunk [128 x 64] with fused fp32 -> bf16 hi/lo split
        for (int i = t; i < 128 * 16; i += 256) {
            int r = i >> 4, c4 = (i & 15) << 2;
            float4 a = make_float4(0.f, 0.f, 0.f, 0.f);
            if (row0 + r < nrows)
                a = *(const float4*)&A[(long)(row0 + r) * HH + kc + c4];
            __nv_bfloat16 hx = __float2bfloat16(a.x);
            __nv_bfloat16 hy = __float2bfloat16(a.y);
            __nv_bfloat16 hz = __float2bfloat16(a.z);
            __nv_bfloat16 hw = __float2bfloat16(a.w);
            __nv_bfloat162 hv0 = __nv_bfloat162(hx, hy);
            __nv_bfloat162 hv1 = __nv_bfloat162(hz, hw);
            __nv_bfloat162 lv0 = __nv_bfloat162(
                __float2bfloat16(a.x - __bfloat162float(hx)),
                __float2bfloat16(a.y - __bfloat162float(hy)));
            __nv_bfloat162 lv1 = __nv_bfloat162(
                __float2bfloat16(a.z - __bfloat162float(hz)),
                __float2bfloat16(a.w - __bfloat162float(hw)));
            *(__nv_bfloat162*)&sAh[r * BLD + c4]     = hv0;
            *(__nv_bfloat162*)&sAh[r * BLD + c4 + 2] = hv1;
            *(__nv_bfloat162*)&sAl[r * BLD + c4]     = lv0;
            *(__nv_bfloat162*)&sAl[r * BLD + c4 + 2] = lv1;
        }
        // stage W chunk [64 x 64] (pre-split bf16 in global, 16B copies)
        for (int i = t; i < 64 * 8; i += 256) {
            int r = i >> 3, c8 = (i & 7) << 3;
            *(uint4*)&sWh[r * BLD + c8] =
                *(const uint4*)&Whi[(long)(kc + r) * HH + col0 + c8];
            *(uint4*)&sWl[r * BLD + c8] =
                *(const uint4*)&Wlo[(long)(kc + r) * HH + col0 + c8];
        }
        __syncthreads();

#pragma unroll
        for (int kk = 0; kk < 64; kk += 16) {
            wmma::load_matrix_sync(ah, &sAh[(w * 16) * BLD + kk], BLD);
            wmma::load_matrix_sync(al, &sAl[(w * 16) * BLD + kk], BLD);
#pragma unroll
            for (int j = 0; j < 4; j++) {
                wmma::load_matrix_sync(bh, &sWh[kk * BLD + j * 16], BLD);
                wmma::load_matrix_sync(bl, &sWl[kk * BLD + j * 16], BLD);
                wmma::mma_sync(acc[j], ah, bh, acc[j]);
                wmma::mma_sync(acc[j], ah, bl, acc[j]);
                wmma::mma_sync(acc[j], al, bh, acc[j]);
            }
        }
        __syncthreads();
    }

    // epilogue via smem reinterpreted as fp32 (128 x 68 = 34.8KB < 36KB A region)
    float* sepi = (float*)smem;
#pragma unroll
    for (int j = 0; j < 4; j++)
        wmma::store_matrix_sync(&sepi[(w * 16) * 68 + j * 16], acc[j], 68,
                                wmma::mem_row_major);
    __syncthreads();

    int r = t >> 1;
    int ch = (t & 1) * 32;
    int row = row0 + r;
    const float* srow = &sepi[r * 68 + ch];
    float ps = 0.f, pd = 0.f;
    float4 ov[8];
#pragma unroll
    for (int q = 0; q < 8; q++) {
        float4 v = make_float4(srow[q * 4], srow[q * 4 + 1],
                               srow[q * 4 + 2], srow[q * 4 + 3]);
        int c = col0 + ch + q * 4;
        if (bias) {
            v.x += bias[c]; v.y += bias[c + 1]; v.z += bias[c + 2]; v.w += bias[c + 3];
        }
        if (a_s) {
            ps += v.x * a_s[c] + v.y * a_s[c + 1] + v.z * a_s[c + 2] + v.w * a_s[c + 3];
            pd += v.x * a_d[c] + v.y * a_d[c + 1] + v.z * a_d[c + 2] + v.w * a_d[c + 3];
        }
        ov[q] = v;
    }
    if (a_s) {
        ps += __shfl_xor_sync(0xffffffffu, ps, 1);
        pd += __shfl_xor_sync(0xffffffffu, pd, 1);
    }
    if (row < nrows) {
#pragma unroll
        for (int q = 0; q < 8; q++)
            *(float4*)&C[(long)row * HH + col0 + ch + q * 4] = ov[q];
        if (a_s && (t & 1) == 0) {
            asp[row + blockIdx.y * nrows]             = ps;
            asp[row + 2 * nrows + blockIdx.y * nrows] = pd;
        }
    }
}

// combine the two col-block partials: asum[i] = as, asum[i+n] = ad
__global__ void k_combine(const float* __restrict__ asp, float* __restrict__ asum,
                          int n) {
    int i = blockIdx.x * blockDim.x + threadIdx.x;
    if (i >= n) return;
    asum[i]     = asp[i] + asp[i + n];
    asum[i + n] = asp[i + 2 * n] + asp[i + 3 * n];
}

// warp per destination node; two-pass softmax with edge-score buffer.
__global__ __launch_bounds__(256) void k_aggregate(
    const int* __restrict__ rowptr, const int* __restrict__ col,
    const float* __restrict__ asum, float* __restrict__ ev,
    const float* __restrict__ hp, const float* __restrict__ bias,
    float* __restrict__ hout, int n, int relu) {
    int gid = blockIdx.x * blockDim.x + threadIdx.x;
    int w = gid >> 5, lane = gid & 31;
    if (w >= n) return;
    int beg = rowptr[w], end = rowptr[w + 1];
    float add = __ldg(&asum[w + n]);

    float m = -3.4e38f, den = 0.f;
    for (int j = beg + lane; j < end; j += 32) {
        float v = __ldg(&asum[__ldg(&col[j])]) + add;
        v = v >= 0.f ? v : 0.2f * v;
        ev[j] = v;
        if (v > m) { den = den * __expf(m - v) + 1.f; m = v; }
        else den += __expf(v - m);
    }
#pragma unroll
    for (int o = 16; o > 0; o >>= 1) {
        float mo = __shfl_xor_sync(0xffffffffu, m, o);
        float dd = __shfl_xor_sync(0xffffffffu, den, o);
        float M = fmaxf(m, mo);
        den = den * __expf(m - M) + dd * __expf(mo - M);
        m = M;
    }
    float inv = 1.f / den;

    float4 acc = make_float4(0.f, 0.f, 0.f, 0.f);
    int j = beg;
#pragma unroll 1
    for (; j + 4 <= end; j += 4) {
        int   s0 = __ldg(&col[j]),     s1 = __ldg(&col[j + 1]);
        int   s2 = __ldg(&col[j + 2]), s3 = __ldg(&col[j + 3]);
        float a0 = __expf(ev[j]     - m) * inv;
        float a1 = __expf(ev[j + 1] - m) * inv;
        float a2 = __expf(ev[j + 2] - m) * inv;
        float a3 = __expf(ev[j + 3] - m) * inv;
        float4 h0 = __ldg(&((const float4*)hp)[(long)s0 * 32 + lane]);
        float4 h1 = __ldg(&((const float4*)hp)[(long)s1 * 32 + lane]);
        float4 h2 = __ldg(&((const float4*)hp)[(long)s2 * 32 + lane]);
        float4 h3 = __ldg(&((const float4*)hp)[(long)s3 * 32 + lane]);
        acc.x = fmaf(a0, h0.x, acc.x); acc.y = fmaf(a0, h0.y, acc.y);
        acc.z = fmaf(a0, h0.z, acc.z); acc.w = fmaf(a0, h0.w, acc.w);
        acc.x = fmaf(a1, h1.x, acc.x); acc.y = fmaf(a1, h1.y, acc.y);
        acc.z = fmaf(a1, h1.z, acc.z); acc.w = fmaf(a1, h1.w, acc.w);
        acc.x = fmaf(a2, h2.x, acc.x); acc.y = fmaf(a2, h2.y, acc.y);
        acc.z = fmaf(a2, h2.z, acc.z); acc.w = fmaf(a2, h2.w, acc.w);
        acc.x = fmaf(a3, h3.x, acc.x); acc.y = fmaf(a3, h3.y, acc.y);
        acc.z = fmaf(a3, h3.z, acc.z); acc.w = fmaf(a3, h3.w, acc.w);
    }
    for (; j < end; j++) {
        int   s0 = __ldg(&col[j]);
        float a0 = __expf(ev[j] - m) * inv;
        float4 h0 = __ldg(&((const float4*)hp)[(long)s0 * 32 + lane]);
        acc.x = fmaf(a0, h0.x, acc.x); acc.y = fmaf(a0, h0.y, acc.y);
        acc.z = fmaf(a0, h0.z, acc.z); acc.w = fmaf(a0, h0.w, acc.w);
    }
    float4 bb = ((const float4*)bias)[lane];
    acc.x += bb.x; acc.y += bb.y; acc.z += bb.z; acc.w += bb.w;
    if (relu) {
        acc.x = fmaxf(acc.x, 0.f); acc.y = fmaxf(acc.y, 0.f);
        acc.z = fmaxf(acc.z, 0.f); acc.w = fmaxf(acc.w, 0.f);
    }
    ((float4*)hout)[(long)w * 32 + lane] = acc;
}

// global_add_pool over sorted batch
__global__ void k_pool(const float* __restrict__ h, const void* batch,
                       float* __restrict__ pool, int n) {
    __shared__ float s[GG * HH];
    for (int i = threadIdx.x; i < GG * HH; i += 256) s[i] = 0.f;
    __syncthreads();
    int is64 = g_is64;
    int per = (n + gridDim.x - 1) / gridDim.x;
    int i0 = blockIdx.x * per;
    int i1 = min(n, i0 + per);
    int c = threadIdx.x & 127, sub = threadIdx.x >> 7;
    float accv = 0.f; int curg = -1;
    for (int r = i0 + sub; r < i1; r += 2) {
        int g = ld_idx(batch, r, is64);
        if (g != curg) {
            if (curg >= 0) atomicAdd(&s[curg * HH + c], accv);
            accv = 0.f; curg = g;
        }
        accv += h[(long)r * HH + c];
    }
    if (curg >= 0) atomicAdd(&s[curg * HH + c], accv);
    __syncthreads();
    for (int i = threadIdx.x; i < GG * HH; i += 256) {
        float v = s[i];
        if (v != 0.f) atomicAdd(&pool[i], v);
    }
}

__global__ void k_final(const float* __restrict__ pool, const float* __restrict__ Wf,
                        const float* __restrict__ bf, float* __restrict__ out) {
    int i = blockIdx.x * blockDim.x + threadIdx.x;
    if (i >= GG * OO) return;
    int g = i >> 6, o = i & 63;
    float sa = bf[o];
#pragma unroll 8
    for (int k = 0; k < HH; k++) sa += pool[g * HH + k] * Wf[k * OO + o];
    out[i] = sa;
}

// ---------------- launch ----------------
extern "C" void kernel_launch(void* const* d_in, const int* in_sizes, int n_in,
                              void* d_out, int out_size) {
    const float* x     = (const float*)d_in[0];
    const void*  ei    = d_in[1];
    const void*  batch = d_in[2];
    const float* W0    = (const float*)d_in[3];
    const float* b0    = (const float*)d_in[4];
    const float* Wl    = (const float*)d_in[5];
    const float* a_src = (const float*)d_in[6];
    const float* a_dst = (const float*)d_in[7];
    const float* bl    = (const float*)d_in[8];
    const float* Wf    = (const float*)d_in[9];
    const float* bf    = (const float*)d_in[10];
    float* out = (float*)d_out;

    int n  = in_sizes[0] / HH;
    int E  = in_sizes[1] / 2;
    int et = E + n;
    int L  = in_sizes[5] / (HH * HH);

    float *h, *hp, *asp, *asum, *ev, *pool;
    __nv_bfloat16 *whi, *wlo;
    int *counts, *part, *rowptr, *fillp, *bsum, *col;
    cudaGetSymbolAddress((void**)&h,    g_h);
    cudaGetSymbolAddress((void**)&hp,   g_hp);
    cudaGetSymbolAddress((void**)&whi,  g_whi);
    cudaGetSymbolAddress((void**)&wlo,  g_wlo);
    cudaGetSymbolAddress((void**)&asp,  g_asp);
    cudaGetSymbolAddress((void**)&asum, g_asum);
    cudaGetSymbolAddress((void**)&ev,   g_ev);
    cudaGetSymbolAddress((void**)&pool, g_pool);
    cudaGetSymbolAddress((void**)&counts, g_counts);
    cudaGetSymbolAddress((void**)&part,   g_part);
    cudaGetSymbolAddress((void**)&rowptr, g_rowptr);
    cudaGetSymbolAddress((void**)&fillp,  g_fillp);
    cudaGetSymbolAddress((void**)&bsum,   g_bsum);
    cudaGetSymbolAddress((void**)&col,    g_col);

    cudaFuncSetAttribute(k_gemm_bf, cudaFuncAttributeMaxDynamicSharedMemorySize,
                         GEMM_SMEM);

    dim3 tg((n + 127) / 128, 2);
    int nb = (n + 1023) / 1024;

    // slots 1-3 (slot 4 = k_gemm_bf profiled by ncu -s 5 -c 1)
    k_splitW<<<((L + 1) * HH * HH + 255) / 256, 256>>>(W0, Wl, whi, wlo, L);
    k_detect<<<1, 32>>>((const unsigned long long*)ei);
    k_zero_i<<<(n + 255) / 256, 256>>>(counts, n);

    // slot 4: h = x @ W0 + b0
    k_gemm_bf<<<tg, 256, GEMM_SMEM>>>(x, whi, wlo, b0, nullptr, nullptr, nullptr, h, n);

    // CSR build
    k_hist<<<(et + 255) / 256, 256>>>(ei, counts, E, n);
    k_scanA<<<nb, 1024>>>(counts, part, bsum, n);
    k_scanC<<<(n + 255) / 256, 256>>>(part, bsum, counts, rowptr, fillp, n);
    k_fill<<<(et + 255) / 256, 256>>>(ei, fillp, col, E, n);

    for (int l = 0; l < L; l++) {
        k_gemm_bf<<<tg, 256, GEMM_SMEM>>>(h, whi + (long)(l + 1) * HH * HH,
                                          wlo + (long)(l + 1) * HH * HH, nullptr,
                                          a_src + l * HH, a_dst + l * HH,
                                          asp, hp, n);
        k_combine<<<(n + 255) / 256, 256>>>(asp, asum, n);
        k_aggregate<<<(n * 32 + 255) / 256, 256>>>(rowptr, col, asum, ev, hp,
                                                   bl + l * HH, h, n,
                                                   (l < L - 1) ? 1 : 0);
    }

    k_zero<<<(GG * HH / 4 + 255) / 256, 256>>>((float4*)pool, GG * HH / 4);
    k_pool<<<64, 256>>>(h, batch, pool, n);
    k_final<<<(GG * OO + 255) / 256, 256>>>(pool, Wf, bf, out);
}

// round 9
// speedup vs baseline: 1.6347x; 1.0334x over previous
#include <cuda_runtime.h>
#include <cuda_bf16.h>
#include <cuda_fp16.h>
#include <mma.h>
using namespace nvcuda;

// Problem shape (fixed per dataset)
#define MAXN 50000
#define MAXE 800000
#define HH   128
#define GG   64
#define OO   64

// ---------------- scratch (static device globals; no allocs) ----------------
__device__ __align__(128) float          g_h   [MAXN * HH];
__device__ __align__(128) __half         g_hp16[MAXN * HH];
__device__ __align__(128) __nv_bfloat16  g_whi [4 * HH * HH];
__device__ __align__(128) __nv_bfloat16  g_wlo [4 * HH * HH];
__device__ __align__(128) float          g_asp [4 * MAXN];
__device__ __align__(128) float          g_asum[2 * MAXN];
__device__ __align__(128) float          g_ev  [MAXE + MAXN];
__device__ __align__(128) float          g_pool[GG * HH];
// CSR scratch
__device__ __align__(128) int g_counts[MAXN];
__device__ __align__(128) int g_part  [MAXN];
__device__ __align__(128) int g_rowptr[MAXN + 1];
__device__ __align__(128) int g_fillp [MAXN];
__device__ __align__(128) int g_bsum  [256];
__device__ __align__(128) int g_col   [MAXE + MAXN];
__device__ int g_is64;

// ---------------- helpers ----------------
__device__ __forceinline__ int ld_idx(const void* p, long i, int is64) {
    if (is64) return (int)((const long long*)p)[i];
    return ((const int*)p)[i];
}
__device__ __forceinline__ float4 hp16_ld(const __half* base, long s, int lane) {
    uint2 u = __ldg((const uint2*)(base + s * HH + lane * 4));
    __half2 p0 = *(__half2*)&u.x;
    __half2 p1 = *(__half2*)&u.y;
    float2 f0 = __half22float2(p0);
    float2 f1 = __half22float2(p1);
    return make_float4(f0.x, f0.y, f1.x, f1.y);
}

// ---------------- kernels ----------------

__global__ void k_detect(const unsigned long long* ei) {
    if (threadIdx.x == 0 && blockIdx.x == 0) {
        int is64 = 1;
        for (int i = 0; i < 64; i++)
            if (ei[i] > 1000000ull) is64 = 0;
        g_is64 = is64;
    }
}

__global__ void k_zero_i(int* p, int n) {
    int i = blockIdx.x * blockDim.x + threadIdx.x;
    if (i < n) p[i] = 0;
}
__global__ void k_zero(float4* p, int n4) {
    int i = blockIdx.x * blockDim.x + threadIdx.x;
    if (i < n4) p[i] = make_float4(0.f, 0.f, 0.f, 0.f);
}

// split W0 + all Wl layers into bf16 hi/lo (once)
__global__ void k_splitW(const float* __restrict__ W0, const float* __restrict__ Wl,
                         __nv_bfloat16* __restrict__ whi,
                         __nv_bfloat16* __restrict__ wlo, int L) {
    int i = blockIdx.x * blockDim.x + threadIdx.x;
    int total = (L + 1) * HH * HH;
    if (i >= total) return;
    float v = (i < HH * HH) ? W0[i] : Wl[i - HH * HH];
    __nv_bfloat16 h = __float2bfloat16(v);
    whi[i] = h;
    wlo[i] = __float2bfloat16(v - __bfloat162float(h));
}

// ---- CSR build (once per launch) ----
__global__ void k_hist(const void* ei, int* counts, int E, int n) {
    int e = blockIdx.x * blockDim.x + threadIdx.x;
    if (e >= E + n) return;
    int d = (e < E) ? ld_idx(ei, (long)E + e, g_is64) : (e - E);
    atomicAdd(&counts[d], 1);
}

__global__ __launch_bounds__(1024) void k_scanA(const int* counts, int* part,
                                                int* bsum, int n) {
    __shared__ int ws[32];
    int i = blockIdx.x * 1024 + threadIdx.x;
    int lane = threadIdx.x & 31, wid = threadIdx.x >> 5;
    int x = (i < n) ? counts[i] : 0;
#pragma unroll
    for (int o = 1; o < 32; o <<= 1) {
        int y = __shfl_up_sync(0xffffffffu, x, o);
        if (lane >= o) x += y;
    }
    if (lane == 31) ws[wid] = x;
    __syncthreads();
    if (wid == 0) {
        int y = ws[lane];
#pragma unroll
        for (int o = 1; o < 32; o <<= 1) {
            int z = __shfl_up_sync(0xffffffffu, y, o);
            if (lane >= o) y += z;
        }
        ws[lane] = y;
    }
    __syncthreads();
    int incl = x + (wid ? ws[wid - 1] : 0);
    if (i < n) part[i] = incl;
    if (threadIdx.x == 1023) bsum[blockIdx.x] = incl;
}

__global__ void k_scanC(const int* part, const int* bsum, const int* counts,
                        int* rowptr, int* fillp, int n) {
    __shared__ int pref;
    if (threadIdx.x == 0) {
        int target = blockIdx.x >> 2;
        int run = 0;
        for (int k = 0; k < target; k++) run += bsum[k];
        pref = run;
    }
    __syncthreads();
    int i = blockIdx.x * 256 + threadIdx.x;
    if (i == 0) rowptr[0] = 0;
    if (i < n) {
        int incl = part[i] + pref;
        rowptr[i + 1] = incl;
        fillp[i] = incl - counts[i];
    }
}
__global__ void k_fill(const void* ei, int* fillp, int* col, int E, int n) {
    int e = blockIdx.x * blockDim.x + threadIdx.x;
    if (e >= E + n) return;
    int is64 = g_is64;
    int s, d;
    if (e < E) { s = ld_idx(ei, e, is64); d = ld_idx(ei, (long)E + e, is64); }
    else       { s = d = e - E; }
    int pos = atomicAdd(&fillp[d], 1);
    col[pos] = s;
}

// bf16 split-compensated tensor-core GEMM with smem-staged tiles.
// D = Ah@Wh + Ah@Wl + Al@Wh. Block tile 128x64, K chunks of 64, 8 warps.
// Output: fp32 C (if C != nullptr) or fp16 C16. Fused bias + alpha partials.
#define BLD 72
#define GEMM_SMEM ((2 * 128 * BLD + 2 * 64 * BLD) * (int)sizeof(__nv_bfloat16))
__global__ __launch_bounds__(256, 3) void k_gemm_bf(
    const float* __restrict__ A,
    const __nv_bfloat16* __restrict__ Whi, const __nv_bfloat16* __restrict__ Wlo,
    const float* __restrict__ bias,
    const float* __restrict__ a_s, const float* __restrict__ a_d,
    float* __restrict__ asp, float* __restrict__ C,
    __half* __restrict__ C16, int nrows) {
    extern __shared__ __nv_bfloat16 smem[];
    __nv_bfloat16* sAh = smem;
    __nv_bfloat16* sAl = sAh + 128 * BLD;
    __nv_bfloat16* sWh = sAl + 128 * BLD;
    __nv_bfloat16* sWl = sWh + 64 * BLD;

    int t = threadIdx.x;
    int w = t >> 5;
    int row0 = blockIdx.x * 128;
    int col0 = blockIdx.y * 64;

    wmma::fragment<wmma::accumulator, 16, 16, 16, float> acc[4];
#pragma unroll
    for (int j = 0; j < 4; j++) wmma::fill_fragment(acc[j], 0.f);
    wmma::fragment<wmma::matrix_a, 16, 16, 16, __nv_bfloat16, wmma::row_major> ah, al;
    wmma::fragment<wmma::matrix_b, 16, 16, 16, __nv_bfloat16, wmma::row_major> bh, bl;

    for (int kc = 0; kc < HH; kc += 64) {
        for (int i = t; i < 128 * 16; i += 256) {
            int r = i >> 4, c4 = (i & 15) << 2;
            float4 a = make_float4(0.f, 0.f, 0.f, 0.f);
            if (row0 + r < nrows)
                a = *(const float4*)&A[(long)(row0 + r) * HH + kc + c4];
            __nv_bfloat16 hx = __float2bfloat16(a.x);
            __nv_bfloat16 hy = __float2bfloat16(a.y);
            __nv_bfloat16 hz = __float2bfloat16(a.z);
            __nv_bfloat16 hw = __float2bfloat16(a.w);
            __nv_bfloat162 hv0 = __nv_bfloat162(hx, hy);
            __nv_bfloat162 hv1 = __nv_bfloat162(hz, hw);
            __nv_bfloat162 lv0 = __nv_bfloat162(
                __float2bfloat16(a.x - __bfloat162float(hx)),
                __float2bfloat16(a.y - __bfloat162float(hy)));
            __nv_bfloat162 lv1 = __nv_bfloat162(
                __float2bfloat16(a.z - __bfloat162float(hz)),
                __float2bfloat16(a.w - __bfloat162float(hw)));
            *(__nv_bfloat162*)&sAh[r * BLD + c4]     = hv0;
            *(__nv_bfloat162*)&sAh[r * BLD + c4 + 2] = hv1;
            *(__nv_bfloat162*)&sAl[r * BLD + c4]     = lv0;
            *(__nv_bfloat162*)&sAl[r * BLD + c4 + 2] = lv1;
        }
        for (int i = t; i < 64 * 8; i += 256) {
            int r = i >> 3, c8 = (i & 7) << 3;
            *(uint4*)&sWh[r * BLD + c8] =
                *(const uint4*)&Whi[(long)(kc + r) * HH + col0 + c8];
            *(uint4*)&sWl[r * BLD + c8] =
                *(const uint4*)&Wlo[(long)(kc + r) * HH + col0 + c8];
        }
        __syncthreads();

#pragma unroll
        for (int kk = 0; kk < 64; kk += 16) {
            wmma::load_matrix_sync(ah, &sAh[(w * 16) * BLD + kk], BLD);
            wmma::load_matrix_sync(al, &sAl[(w * 16) * BLD + kk], BLD);
#pragma unroll
            for (int j = 0; j < 4; j++) {
                wmma::load_matrix_sync(bh, &sWh[kk * BLD + j * 16], BLD);
                wmma::load_matrix_sync(bl, &sWl[kk * BLD + j * 16], BLD);
                wmma::mma_sync(acc[j], ah, bh, acc[j]);
                wmma::mma_sync(acc[j], ah, bl, acc[j]);
                wmma::mma_sync(acc[j], al, bh, acc[j]);
            }
        }
        __syncthreads();
    }

    float* sepi = (float*)smem;
#pragma unroll
    for (int j = 0; j < 4; j++)
        wmma::store_matrix_sync(&sepi[(w * 16) * 68 + j * 16], acc[j], 68,
                                wmma::mem_row_major);
    __syncthreads();

    int r = t >> 1;
    int ch = (t & 1) * 32;
    int row = row0 + r;
    const float* srow = &sepi[r * 68 + ch];
    float ps = 0.f, pd = 0.f;
    float4 ov[8];
#pragma unroll
    for (int q = 0; q < 8; q++) {
        float4 v = make_float4(srow[q * 4], srow[q * 4 + 1],
                               srow[q * 4 + 2], srow[q * 4 + 3]);
        int c = col0 + ch + q * 4;
        if (bias) {
            v.x += bias[c]; v.y += bias[c + 1]; v.z += bias[c + 2]; v.w += bias[c + 3];
        }
        if (a_s) {
            ps += v.x * a_s[c] + v.y * a_s[c + 1] + v.z * a_s[c + 2] + v.w * a_s[c + 3];
            pd += v.x * a_d[c] + v.y * a_d[c + 1] + v.z * a_d[c + 2] + v.w * a_d[c + 3];
        }
        ov[q] = v;
    }
    if (a_s) {
        ps += __shfl_xor_sync(0xffffffffu, ps, 1);
        pd += __shfl_xor_sync(0xffffffffu, pd, 1);
    }
    if (row < nrows) {
        if (C) {
#pragma unroll
            for (int q = 0; q < 8; q++)
                *(float4*)&C[(long)row * HH + col0 + ch + q * 4] = ov[q];
        }
        if (C16) {
#pragma unroll
            for (int q = 0; q < 8; q++) {
                __half2 ha = __floats2half2_rn(ov[q].x, ov[q].y);
                __half2 hb = __floats2half2_rn(ov[q].z, ov[q].w);
                uint2 pk;
                pk.x = *(unsigned*)&ha;
                pk.y = *(unsigned*)&hb;
                *(uint2*)&C16[(long)row * HH + col0 + ch + q * 4] = pk;
            }
        }
        if (a_s && (t & 1) == 0) {
            asp[row + blockIdx.y * nrows]             = ps;
            asp[row + 2 * nrows + blockIdx.y * nrows] = pd;
        }
    }
}

// combine the two col-block partials
__global__ void k_combine(const float* __restrict__ asp, float* __restrict__ asum,
                          int n) {
    int i = blockIdx.x * blockDim.x + threadIdx.x;
    if (i >= n) return;
    asum[i]     = asp[i] + asp[i + n];
    asum[i + n] = asp[i + 2 * n] + asp[i + 3 * n];
}

// warp per destination node; two-pass softmax; fp16 hp gather.
__global__ __launch_bounds__(256) void k_aggregate(
    const int* __restrict__ rowptr, const int* __restrict__ col,
    const float* __restrict__ asum, float* __restrict__ ev,
    const __half* __restrict__ hp16, const float* __restrict__ bias,
    float* __restrict__ hout, int n, int relu) {
    int gid = blockIdx.x * blockDim.x + threadIdx.x;
    int w = gid >> 5, lane = gid & 31;
    if (w >= n) return;
    int beg = rowptr[w], end = rowptr[w + 1];
    float add = __ldg(&asum[w + n]);

    float m = -3.4e38f, den = 0.f;
    for (int j = beg + lane; j < end; j += 32) {
        float v = __ldg(&asum[__ldg(&col[j])]) + add;
        v = v >= 0.f ? v : 0.2f * v;
        ev[j] = v;
        if (v > m) { den = den * __expf(m - v) + 1.f; m = v; }
        else den += __expf(v - m);
    }
#pragma unroll
    for (int o = 16; o > 0; o >>= 1) {
        float mo = __shfl_xor_sync(0xffffffffu, m, o);
        float dd = __shfl_xor_sync(0xffffffffu, den, o);
        float M = fmaxf(m, mo);
        den = den * __expf(m - M) + dd * __expf(mo - M);
        m = M;
    }
    float inv = 1.f / den;

    float4 acc = make_float4(0.f, 0.f, 0.f, 0.f);
    int j = beg;
#pragma unroll 1
    for (; j + 4 <= end; j += 4) {
        int   s0 = __ldg(&col[j]),     s1 = __ldg(&col[j + 1]);
        int   s2 = __ldg(&col[j + 2]), s3 = __ldg(&col[j + 3]);
        float a0 = __expf(ev[j]     - m) * inv;
        float a1 = __expf(ev[j + 1] - m) * inv;
        float a2 = __expf(ev[j + 2] - m) * inv;
        float a3 = __expf(ev[j + 3] - m) * inv;
        float4 h0 = hp16_ld(hp16, s0, lane);
        float4 h1 = hp16_ld(hp16, s1, lane);
        float4 h2 = hp16_ld(hp16, s2, lane);
        float4 h3 = hp16_ld(hp16, s3, lane);
        acc.x = fmaf(a0, h0.x, acc.x); acc.y = fmaf(a0, h0.y, acc.y);
        acc.z = fmaf(a0, h0.z, acc.z); acc.w = fmaf(a0, h0.w, acc.w);
        acc.x = fmaf(a1, h1.x, acc.x); acc.y = fmaf(a1, h1.y, acc.y);
        acc.z = fmaf(a1, h1.z, acc.z); acc.w = fmaf(a1, h1.w, acc.w);
        acc.x = fmaf(a2, h2.x, acc.x); acc.y = fmaf(a2, h2.y, acc.y);
        acc.z = fmaf(a2, h2.z, acc.z); acc.w = fmaf(a2, h2.w, acc.w);
        acc.x = fmaf(a3, h3.x, acc.x); acc.y = fmaf(a3, h3.y, acc.y);
        acc.z = fmaf(a3, h3.z, acc.z); acc.w = fmaf(a3, h3.w, acc.w);
    }
    for (; j < end; j++) {
        int   s0 = __ldg(&col[j]);
        float a0 = __expf(ev[j] - m) * inv;
        float4 h0 = hp16_ld(hp16, s0, lane);
        acc.x = fmaf(a0, h0.x, acc.x); acc.y = fmaf(a0, h0.y, acc.y);
        acc.z = fmaf(a0, h0.z, acc.z); acc.w = fmaf(a0, h0.w, acc.w);
    }
    float4 bb = ((const float4*)bias)[lane];
    acc.x += bb.x; acc.y += bb.y; acc.z += bb.z; acc.w += bb.w;
    if (relu) {
        acc.x = fmaxf(acc.x, 0.f); acc.y = fmaxf(acc.y, 0.f);
        acc.z = fmaxf(acc.z, 0.f); acc.w = fmaxf(acc.w, 0.f);
    }
    ((float4*)hout)[(long)w * 32 + lane] = acc;
}

// global_add_pool over sorted batch
__global__ void k_pool(const float* __restrict__ h, const void* batch,
                       float* __restrict__ pool, int n) {
    __shared__ float s[GG * HH];
    for (int i = threadIdx.x; i < GG * HH; i += 256) s[i] = 0.f;
    __syncthreads();
    int is64 = g_is64;
    int per = (n + gridDim.x - 1) / gridDim.x;
    int i0 = blockIdx.x * per;
    int i1 = min(n, i0 + per);
    int c = threadIdx.x & 127, sub = threadIdx.x >> 7;
    float accv = 0.f; int curg = -1;
    for (int r = i0 + sub; r < i1; r += 2) {
        int g = ld_idx(batch, r, is64);
        if (g != curg) {
            if (curg >= 0) atomicAdd(&s[curg * HH + c], accv);
            accv = 0.f; curg = g;
        }
        accv += h[(long)r * HH + c];
    }
    if (curg >= 0) atomicAdd(&s[curg * HH + c], accv);
    __syncthreads();
    for (int i = threadIdx.x; i < GG * HH; i += 256) {
        float v = s[i];
        if (v != 0.f) atomicAdd(&pool[i], v);
    }
}

__global__ void k_final(const float* __restrict__ pool, const float* __restrict__ Wf,
                        const float* __restrict__ bf, float* __restrict__ out) {
    int i = blockIdx.x * blockDim.x + threadIdx.x;
    if (i >= GG * OO) return;
    int g = i >> 6, o = i & 63;
    float sa = bf[o];
#pragma unroll 8
    for (int k = 0; k < HH; k++) sa += pool[g * HH + k] * Wf[k * OO + o];
    out[i] = sa;
}

// ---------------- launch ----------------
extern "C" void kernel_launch(void* const* d_in, const int* in_sizes, int n_in,
                              void* d_out, int out_size) {
    const float* x     = (const float*)d_in[0];
    const void*  ei    = d_in[1];
    const void*  batch = d_in[2];
    const float* W0    = (const float*)d_in[3];
    const float* b0    = (const float*)d_in[4];
    const float* Wl    = (const float*)d_in[5];
    const float* a_src = (const float*)d_in[6];
    const float* a_dst = (const float*)d_in[7];
    const float* bl    = (const float*)d_in[8];
    const float* Wf    = (const float*)d_in[9];
    const float* bf    = (const float*)d_in[10];
    float* out = (float*)d_out;

    int n  = in_sizes[0] / HH;
    int E  = in_sizes[1] / 2;
    int et = E + n;
    int L  = in_sizes[5] / (HH * HH);

    float *h, *asp, *asum, *ev, *pool;
    __half* hp16;
    __nv_bfloat16 *whi, *wlo;
    int *counts, *part, *rowptr, *fillp, *bsum, *col;
    cudaGetSymbolAddress((void**)&h,    g_h);
    cudaGetSymbolAddress((void**)&hp16, g_hp16);
    cudaGetSymbolAddress((void**)&whi,  g_whi);
    cudaGetSymbolAddress((void**)&wlo,  g_wlo);
    cudaGetSymbolAddress((void**)&asp,  g_asp);
    cudaGetSymbolAddress((void**)&asum, g_asum);
    cudaGetSymbolAddress((void**)&ev,   g_ev);
    cudaGetSymbolAddress((void**)&pool, g_pool);
    cudaGetSymbolAddress((void**)&counts, g_counts);
    cudaGetSymbolAddress((void**)&part,   g_part);
    cudaGetSymbolAddress((void**)&rowptr, g_rowptr);
    cudaGetSymbolAddress((void**)&fillp,  g_fillp);
    cudaGetSymbolAddress((void**)&bsum,   g_bsum);
    cudaGetSymbolAddress((void**)&col,    g_col);

    cudaFuncSetAttribute(k_gemm_bf, cudaFuncAttributeMaxDynamicSharedMemorySize,
                         GEMM_SMEM);

    dim3 tg((n + 127) / 128, 2);
    int nb = (n + 1023) / 1024;

    // slots 1-3 (slot 4 = k_gemm_bf profiled by ncu -s 5 -c 1)
    k_splitW<<<((L + 1) * HH * HH + 255) / 256, 256>>>(W0, Wl, whi, wlo, L);
    k_detect<<<1, 32>>>((const unsigned long long*)ei);
    k_zero_i<<<(n + 255) / 256, 256>>>(counts, n);

    // slot 4: h = x @ W0 + b0 (fp32 out)
    k_gemm_bf<<<tg, 256, GEMM_SMEM>>>(x, whi, wlo, b0, nullptr, nullptr, nullptr,
                                      h, nullptr, n);

    // CSR build
    k_hist<<<(et + 255) / 256, 256>>>(ei, counts, E, n);
    k_scanA<<<nb, 1024>>>(counts, part, bsum, n);
    k_scanC<<<(n + 255) / 256, 256>>>(part, bsum, counts, rowptr, fillp, n);
    k_fill<<<(et + 255) / 256, 256>>>(ei, fillp, col, E, n);

    for (int l = 0; l < L; l++) {
        // layer GEMM: fp16 hp out + alpha partials
        k_gemm_bf<<<tg, 256, GEMM_SMEM>>>(h, whi + (long)(l + 1) * HH * HH,
                                          wlo + (long)(l + 1) * HH * HH, nullptr,
                                          a_src + l * HH, a_dst + l * HH,
                                          asp, nullptr, hp16, n);
        k_combine<<<(n + 255) / 256, 256>>>(asp, asum, n);
        k_aggregate<<<(n * 32 + 255) / 256, 256>>>(rowptr, col, asum, ev, hp16,
                                                   bl + l * HH, h, n,
                                                   (l < L - 1) ? 1 : 0);
    }

    k_zero<<<(GG * HH / 4 + 255) / 256, 256>>>((float4*)pool, GG * HH / 4);
    k_pool<<<64, 256>>>(h, batch, pool, n);
    k_final<<<(GG * OO + 255) / 256, 256>>>(pool, Wf, bf, out);
}

// round 12
// speedup vs baseline: 1.7347x; 1.0612x over previous
#include <cuda_runtime.h>
#include <cstdint>
#include <cuda_bf16.h>
#include <cuda_fp16.h>
#include <mma.h>
using namespace nvcuda;

// Problem shape (fixed per dataset)
#define MAXN 50000
#define MAXE 800000
#define HH   128
#define GG   64
#define OO   64

// ---------------- scratch (static device globals; no allocs) ----------------
__device__ __align__(128) float          g_h   [MAXN * HH];
__device__ __align__(128) __half         g_hp16[MAXN * HH];
__device__ __align__(128) __nv_bfloat16  g_whi [4 * HH * HH];
__device__ __align__(128) __nv_bfloat16  g_wlo [4 * HH * HH];
__device__ __align__(128) float          g_asp [4 * MAXN];
__device__ __align__(128) float          g_asum[2 * MAXN];
__device__ __align__(128) float          g_ev  [MAXE + MAXN];
__device__ __align__(128) float          g_pool[GG * HH];
// CSR scratch
__device__ __align__(128) int g_counts[MAXN];
__device__ __align__(128) int g_part  [MAXN];
__device__ __align__(128) int g_rowptr[MAXN + 1];
__device__ __align__(128) int g_fillp [MAXN];
__device__ __align__(128) int g_bsum  [256];
__device__ __align__(128) int g_col   [MAXE + MAXN];
__device__ int g_is64;

// ---------------- helpers ----------------
__device__ __forceinline__ int ld_idx(const void* p, long i, int is64) {
    if (is64) return (int)((const long long*)p)[i];
    return ((const int*)p)[i];
}
__device__ __forceinline__ float4 hp16_ld(const __half* base, long s, int lane) {
    uint2 u = __ldg((const uint2*)(base + s * HH + lane * 4));
    __half2 p0 = *(__half2*)&u.x;
    __half2 p1 = *(__half2*)&u.y;
    float2 f0 = __half22float2(p0);
    float2 f1 = __half22float2(p1);
    return make_float4(f0.x, f0.y, f1.x, f1.y);
}

// ---------------- kernels ----------------

__global__ void k_detect(const unsigned long long* ei) {
    if (threadIdx.x == 0 && blockIdx.x == 0) {
        int is64 = 1;
        for (int i = 0; i < 64; i++)
            if (ei[i] > 1000000ull) is64 = 0;
        g_is64 = is64;
    }
}

__global__ void k_zero_i(int* p, int n) {
    int i = blockIdx.x * blockDim.x + threadIdx.x;
    if (i < n) p[i] = 0;
}
__global__ void k_zero(float4* p, int n4) {
    int i = blockIdx.x * blockDim.x + threadIdx.x;
    if (i < n4) p[i] = make_float4(0.f, 0.f, 0.f, 0.f);
}

// split W0 + all Wl layers into bf16 hi/lo (once)
__global__ void k_splitW(const float* __restrict__ W0, const float* __restrict__ Wl,
                         __nv_bfloat16* __restrict__ whi,
                         __nv_bfloat16* __restrict__ wlo, int L) {
    int i = blockIdx.x * blockDim.x + threadIdx.x;
    int total = (L + 1) * HH * HH;
    if (i >= total) return;
    float v = (i < HH * HH) ? W0[i] : Wl[i - HH * HH];
    __nv_bfloat16 h = __float2bfloat16(v);
    whi[i] = h;
    wlo[i] = __float2bfloat16(v - __bfloat162float(h));
}

// ---- CSR build ----
__global__ void k_hist(const void* ei, int* counts, int E, int n) {
    int e = blockIdx.x * blockDim.x + threadIdx.x;
    if (e >= E + n) return;
    int d = (e < E) ? ld_idx(ei, (long)E + e, g_is64) : (e - E);
    atomicAdd(&counts[d], 1);
}

__global__ __launch_bounds__(1024) void k_scanA(const int* counts, int* part,
                                                int* bsum, int n) {
    __shared__ int ws[32];
    int i = blockIdx.x * 1024 + threadIdx.x;
    int lane = threadIdx.x & 31, wid = threadIdx.x >> 5;
    int x = (i < n) ? counts[i] : 0;
#pragma unroll
    for (int o = 1; o < 32; o <<= 1) {
        int y = __shfl_up_sync(0xffffffffu, x, o);
        if (lane >= o) x += y;
    }
    if (lane == 31) ws[wid] = x;
    __syncthreads();
    if (wid == 0) {
        int y = ws[lane];
#pragma unroll
        for (int o = 1; o < 32; o <<= 1) {
            int z = __shfl_up_sync(0xffffffffu, y, o);
            if (lane >= o) y += z;
        }
        ws[lane] = y;
    }
    __syncthreads();
    int incl = x + (wid ? ws[wid - 1] : 0);
    if (i < n) part[i] = incl;
    if (threadIdx.x == 1023) bsum[blockIdx.x] = incl;
}

__global__ void k_scanC(const int* part, const int* bsum, const int* counts,
                        int* rowptr, int* fillp, int n) {
    __shared__ int pref;
    if (threadIdx.x == 0) {
        int target = blockIdx.x >> 2;
        int run = 0;
        for (int k = 0; k < target; k++) run += bsum[k];
        pref = run;
    }
    __syncthreads();
    int i = blockIdx.x * 256 + threadIdx.x;
    if (i == 0) rowptr[0] = 0;
    if (i < n) {
        int incl = part[i] + pref;
        rowptr[i + 1] = incl;
        fillp[i] = incl - counts[i];
    }
}
__global__ void k_fill(const void* ei, int* fillp, int* col, int E, int n) {
    int e = blockIdx.x * blockDim.x + threadIdx.x;
    if (e >= E + n) return;
    int is64 = g_is64;
    int s, d;
    if (e < E) { s = ld_idx(ei, e, is64); d = ld_idx(ei, (long)E + e, is64); }
    else       { s = d = e - E; }
    int pos = atomicAdd(&fillp[d], 1);
    col[pos] = s;
}

// bf16 split-compensated tensor-core GEMM (HMMA; tcgen05 unavailable — harness
// targets sm_103 without the 'a' feature set).
// D = Ah@Wh + Ah@Wl + Al@Wh. Block tile 128x64, K chunks of 64, 8 warps in a
// 4x2 grid (warp tile 32x32 — fewer LDSM per MMA than 16x64).
// __launch_bounds__(256,4): regs<=64 so 4 blocks/SM (smem 54KB*4 fits).
#define BLD 72
#define GEMM_SMEM ((2 * 128 * BLD + 2 * 64 * BLD) * (int)sizeof(__nv_bfloat16))
__global__ __launch_bounds__(256, 4) void k_gemm_bf(
    const float* __restrict__ A,
    const __nv_bfloat16* __restrict__ Whi, const __nv_bfloat16* __restrict__ Wlo,
    const float* __restrict__ bias,
    const float* __restrict__ a_s, const float* __restrict__ a_d,
    float* __restrict__ asp, float* __restrict__ C,
    __half* __restrict__ C16, int nrows) {
    extern __shared__ __nv_bfloat16 smem[];
    __nv_bfloat16* sAh = smem;
    __nv_bfloat16* sAl = sAh + 128 * BLD;
    __nv_bfloat16* sWh = sAl + 128 * BLD;
    __nv_bfloat16* sWl = sWh + 64 * BLD;

    int t = threadIdx.x;
    int w = t >> 5;
    int wm = w >> 1, wn = w & 1;         // 4 x 2 warp grid, warp tile 32x32
    int row0 = blockIdx.x * 128;
    int col0 = blockIdx.y * 64;

    wmma::fragment<wmma::accumulator, 16, 16, 16, float> acc[2][2];
#pragma unroll
    for (int i = 0; i < 2; i++)
#pragma unroll
        for (int j = 0; j < 2; j++) wmma::fill_fragment(acc[i][j], 0.f);
    wmma::fragment<wmma::matrix_a, 16, 16, 16, __nv_bfloat16, wmma::row_major> ah[2], al[2];
    wmma::fragment<wmma::matrix_b, 16, 16, 16, __nv_bfloat16, wmma::row_major> bh, bl;

    for (int kc = 0; kc < HH; kc += 64) {
        // stage A chunk [128 x 64] with fused fp32 -> bf16 hi/lo split
        for (int i = t; i < 128 * 16; i += 256) {
            int r = i >> 4, c4 = (i & 15) << 2;
            float4 a = make_float4(0.f, 0.f, 0.f, 0.f);
            if (row0 + r < nrows)
                a = *(const float4*)&A[(long)(row0 + r) * HH + kc + c4];
            __nv_bfloat16 hx = __float2bfloat16(a.x);
            __nv_bfloat16 hy = __float2bfloat16(a.y);
            __nv_bfloat16 hz = __float2bfloat16(a.z);
            __nv_bfloat16 hw = __float2bfloat16(a.w);
            __nv_bfloat162 hv0 = __nv_bfloat162(hx, hy);
            __nv_bfloat162 hv1 = __nv_bfloat162(hz, hw);
            __nv_bfloat162 lv0 = __nv_bfloat162(
                __float2bfloat16(a.x - __bfloat162float(hx)),
                __float2bfloat16(a.y - __bfloat162float(hy)));
            __nv_bfloat162 lv1 = __nv_bfloat162(
                __float2bfloat16(a.z - __bfloat162float(hz)),
                __float2bfloat16(a.w - __bfloat162float(hw)));
            *(__nv_bfloat162*)&sAh[r * BLD + c4]     = hv0;
            *(__nv_bfloat162*)&sAh[r * BLD + c4 + 2] = hv1;
            *(__nv_bfloat162*)&sAl[r * BLD + c4]     = lv0;
            *(__nv_bfloat162*)&sAl[r * BLD + c4 + 2] = lv1;
        }
        // stage W chunk [64 x 64]
        for (int i = t; i < 64 * 8; i += 256) {
            int r = i >> 3, c8 = (i & 7) << 3;
            *(uint4*)&sWh[r * BLD + c8] =
                *(const uint4*)&Whi[(long)(kc + r) * HH + col0 + c8];
            *(uint4*)&sWl[r * BLD + c8] =
                *(const uint4*)&Wlo[(long)(kc + r) * HH + col0 + c8];
        }
        __syncthreads();

#pragma unroll
        for (int kk = 0; kk < 64; kk += 16) {
#pragma unroll
            for (int i = 0; i < 2; i++) {
                wmma::load_matrix_sync(ah[i], &sAh[(wm * 32 + i * 16) * BLD + kk], BLD);
                wmma::load_matrix_sync(al[i], &sAl[(wm * 32 + i * 16) * BLD + kk], BLD);
            }
#pragma unroll
            for (int j = 0; j < 2; j++) {
                wmma::load_matrix_sync(bh, &sWh[kk * BLD + wn * 32 + j * 16], BLD);
                wmma::load_matrix_sync(bl, &sWl[kk * BLD + wn * 32 + j * 16], BLD);
#pragma unroll
                for (int i = 0; i < 2; i++) {
                    wmma::mma_sync(acc[i][j], ah[i], bh, acc[i][j]);
                    wmma::mma_sync(acc[i][j], ah[i], bl, acc[i][j]);
                    wmma::mma_sync(acc[i][j], al[i], bh, acc[i][j]);
                }
            }
        }
        __syncthreads();
    }

    // epilogue via smem reinterpreted as fp32
    float* sepi = (float*)smem;
#pragma unroll
    for (int i = 0; i < 2; i++)
#pragma unroll
        for (int j = 0; j < 2; j++)
            wmma::store_matrix_sync(&sepi[(wm * 32 + i * 16) * 68 + wn * 32 + j * 16],
                                    acc[i][j], 68, wmma::mem_row_major);
    __syncthreads();

    int r = t >> 1;
    int ch = (t & 1) * 32;
    int row = row0 + r;
    const float* srow = &sepi[r * 68 + ch];
    float ps = 0.f, pd = 0.f;
    float4 ov[8];
#pragma unroll
    for (int q = 0; q < 8; q++) {
        float4 v = make_float4(srow[q * 4], srow[q * 4 + 1],
                               srow[q * 4 + 2], srow[q * 4 + 3]);
        int c = col0 + ch + q * 4;
        if (bias) {
            v.x += bias[c]; v.y += bias[c + 1]; v.z += bias[c + 2]; v.w += bias[c + 3];
        }
        if (a_s) {
            ps += v.x * a_s[c] + v.y * a_s[c + 1] + v.z * a_s[c + 2] + v.w * a_s[c + 3];
            pd += v.x * a_d[c] + v.y * a_d[c + 1] + v.z * a_d[c + 2] + v.w * a_d[c + 3];
        }
        ov[q] = v;
    }
    if (a_s) {
        ps += __shfl_xor_sync(0xffffffffu, ps, 1);
        pd += __shfl_xor_sync(0xffffffffu, pd, 1);
    }
    if (row < nrows) {
        if (C) {
#pragma unroll
            for (int q = 0; q < 8; q++)
                *(float4*)&C[(long)row * HH + col0 + ch + q * 4] = ov[q];
        }
        if (C16) {
#pragma unroll
            for (int q = 0; q < 8; q++) {
                __half2 ha = __floats2half2_rn(ov[q].x, ov[q].y);
                __half2 hb = __floats2half2_rn(ov[q].z, ov[q].w);
                uint2 pk;
                pk.x = *(unsigned*)&ha;
                pk.y = *(unsigned*)&hb;
                *(uint2*)&C16[(long)row * HH + col0 + ch + q * 4] = pk;
            }
        }
        if (a_s && (t & 1) == 0) {
            asp[row + blockIdx.y * nrows]             = ps;
            asp[row + 2 * nrows + blockIdx.y * nrows] = pd;
        }
    }
}

// combine the two col-block partials
__global__ void k_combine(const float* __restrict__ asp, float* __restrict__ asum,
                          int n) {
    int i = blockIdx.x * blockDim.x + threadIdx.x;
    if (i >= n) return;
    asum[i]     = asp[i] + asp[i + n];
    asum[i + n] = asp[i + 2 * n] + asp[i + 3 * n];
}

// warp per destination node; two-pass softmax; fp16 hp gather.
__global__ __launch_bounds__(256) void k_aggregate(
    const int* __restrict__ rowptr, const int* __restrict__ col,
    const float* __restrict__ asum, float* __restrict__ ev,
    const __half* __restrict__ hp16, const float* __restrict__ bias,
    float* __restrict__ hout, int n, int relu) {
    int gid = blockIdx.x * blockDim.x + threadIdx.x;
    int w = gid >> 5, lane = gid & 31;
    if (w >= n) return;
    int beg = rowptr[w], end = rowptr[w + 1];
    float add = __ldg(&asum[w + n]);

    float m = -3.4e38f, den = 0.f;
    for (int j = beg + lane; j < end; j += 32) {
        float v = __ldg(&asum[__ldg(&col[j])]) + add;
        v = v >= 0.f ? v : 0.2f * v;
        ev[j] = v;
        if (v > m) { den = den * __expf(m - v) + 1.f; m = v; }
        else den += __expf(v - m);
    }
#pragma unroll
    for (int o = 16; o > 0; o >>= 1) {
        float mo = __shfl_xor_sync(0xffffffffu, m, o);
        float dd = __shfl_xor_sync(0xffffffffu, den, o);
        float M = fmaxf(m, mo);
        den = den * __expf(m - M) + dd * __expf(mo - M);
        m = M;
    }
    float inv = 1.f / den;

    float4 acc = make_float4(0.f, 0.f, 0.f, 0.f);
    int j = beg;
#pragma unroll 1
    for (; j + 4 <= end; j += 4) {
        int   s0 = __ldg(&col[j]),     s1 = __ldg(&col[j + 1]);
        int   s2 = __ldg(&col[j + 2]), s3 = __ldg(&col[j + 3]);
        float a0 = __expf(ev[j]     - m) * inv;
        float a1 = __expf(ev[j + 1] - m) * inv;
        float a2 = __expf(ev[j + 2] - m) * inv;
        float a3 = __expf(ev[j + 3] - m) * inv;
        float4 h0 = hp16_ld(hp16, s0, lane);
        float4 h1 = hp16_ld(hp16, s1, lane);
        float4 h2 = hp16_ld(hp16, s2, lane);
        float4 h3 = hp16_ld(hp16, s3, lane);
        acc.x = fmaf(a0, h0.x, acc.x); acc.y = fmaf(a0, h0.y, acc.y);
        acc.z = fmaf(a0, h0.z, acc.z); acc.w = fmaf(a0, h0.w, acc.w);
        acc.x = fmaf(a1, h1.x, acc.x); acc.y = fmaf(a1, h1.y, acc.y);
        acc.z = fmaf(a1, h1.z, acc.z); acc.w = fmaf(a1, h1.w, acc.w);
        acc.x = fmaf(a2, h2.x, acc.x); acc.y = fmaf(a2, h2.y, acc.y);
        acc.z = fmaf(a2, h2.z, acc.z); acc.w = fmaf(a2, h2.w, acc.w);
        acc.x = fmaf(a3, h3.x, acc.x); acc.y = fmaf(a3, h3.y, acc.y);
        acc.z = fmaf(a3, h3.z, acc.z); acc.w = fmaf(a3, h3.w, acc.w);
    }
    for (; j < end; j++) {
        int   s0 = __ldg(&col[j]);
        float a0 = __expf(ev[j] - m) * inv;
        float4 h0 = hp16_ld(hp16, s0, lane);
        acc.x = fmaf(a0, h0.x, acc.x); acc.y = fmaf(a0, h0.y, acc.y);
        acc.z = fmaf(a0, h0.z, acc.z); acc.w = fmaf(a0, h0.w, acc.w);
    }
    float4 bb = ((const float4*)bias)[lane];
    acc.x += bb.x; acc.y += bb.y; acc.z += bb.z; acc.w += bb.w;
    if (relu) {
        acc.x = fmaxf(acc.x, 0.f); acc.y = fmaxf(acc.y, 0.f);
        acc.z = fmaxf(acc.z, 0.f); acc.w = fmaxf(acc.w, 0.f);
    }
    ((float4*)hout)[(long)w * 32 + lane] = acc;
}

// global_add_pool over sorted batch
__global__ void k_pool(const float* __restrict__ h, const void* batch,
                       float* __restrict__ pool, int n) {
    __shared__ float s[GG * HH];
    for (int i = threadIdx.x; i < GG * HH; i += 256) s[i] = 0.f;
    __syncthreads();
    int is64 = g_is64;
    int per = (n + gridDim.x - 1) / gridDim.x;
    int i0 = blockIdx.x * per;
    int i1 = min(n, i0 + per);
    int c = threadIdx.x & 127, sub = threadIdx.x >> 7;
    float accv = 0.f; int curg = -1;
    for (int r = i0 + sub; r < i1; r += 2) {
        int g = ld_idx(batch, r, is64);
        if (g != curg) {
            if (curg >= 0) atomicAdd(&s[curg * HH + c], accv);
            accv = 0.f; curg = g;
        }
        accv += h[(long)r * HH + c];
    }
    if (curg >= 0) atomicAdd(&s[curg * HH + c], accv);
    __syncthreads();
    for (int i = threadIdx.x; i < GG * HH; i += 256) {
        float v = s[i];
        if (v != 0.f) atomicAdd(&pool[i], v);
    }
}

__global__ void k_final(const float* __restrict__ pool, const float* __restrict__ Wf,
                        const float* __restrict__ bf, float* __restrict__ out) {
    int i = blockIdx.x * blockDim.x + threadIdx.x;
    if (i >= GG * OO) return;
    int g = i >> 6, o = i & 63;
    float sa = bf[o];
#pragma unroll 8
    for (int k = 0; k < HH; k++) sa += pool[g * HH + k] * Wf[k * OO + o];
    out[i] = sa;
}

// ---------------- launch ----------------
extern "C" void kernel_launch(void* const* d_in, const int* in_sizes, int n_in,
                              void* d_out, int out_size) {
    const float* x     = (const float*)d_in[0];
    const void*  ei    = d_in[1];
    const void*  batch = d_in[2];
    const float* W0    = (const float*)d_in[3];
    const float* b0    = (const float*)d_in[4];
    const float* Wl    = (const float*)d_in[5];
    const float* a_src = (const float*)d_in[6];
    const float* a_dst = (const float*)d_in[7];
    const float* bl    = (const float*)d_in[8];
    const float* Wf    = (const float*)d_in[9];
    const float* bf    = (const float*)d_in[10];
    float* out = (float*)d_out;

    int n  = in_sizes[0] / HH;
    int E  = in_sizes[1] / 2;
    int et = E + n;
    int L  = in_sizes[5] / (HH * HH);

    float *h, *asp, *asum, *ev, *pool;
    __half* hp16;
    __nv_bfloat16 *whi, *wlo;
    int *counts, *part, *rowptr, *fillp, *bsum, *col;
    cudaGetSymbolAddress((void**)&h,    g_h);
    cudaGetSymbolAddress((void**)&hp16, g_hp16);
    cudaGetSymbolAddress((void**)&whi,  g_whi);
    cudaGetSymbolAddress((void**)&wlo,  g_wlo);
    cudaGetSymbolAddress((void**)&asp,  g_asp);
    cudaGetSymbolAddress((void**)&asum, g_asum);
    cudaGetSymbolAddress((void**)&ev,   g_ev);
    cudaGetSymbolAddress((void**)&pool, g_pool);
    cudaGetSymbolAddress((void**)&counts, g_counts);
    cudaGetSymbolAddress((void**)&part,   g_part);
    cudaGetSymbolAddress((void**)&rowptr, g_rowptr);
    cudaGetSymbolAddress((void**)&fillp,  g_fillp);
    cudaGetSymbolAddress((void**)&bsum,   g_bsum);
    cudaGetSymbolAddress((void**)&col,    g_col);

    cudaFuncSetAttribute(k_gemm_bf, cudaFuncAttributeMaxDynamicSharedMemorySize,
                         GEMM_SMEM);

    dim3 tg((n + 127) / 128, 2);
    int nb = (n + 1023) / 1024;

    // slots 1-3 (slot 4 = k_gemm_bf profiled by ncu -s 5 -c 1)
    k_splitW<<<((L + 1) * HH * HH + 255) / 256, 256>>>(W0, Wl, whi, wlo, L);
    k_detect<<<1, 32>>>((const unsigned long long*)ei);
    k_zero_i<<<(n + 255) / 256, 256>>>(counts, n);

    // slot 4: h = x @ W0 + b0 (fp32 out)
    k_gemm_bf<<<tg, 256, GEMM_SMEM>>>(x, whi, wlo, b0, nullptr, nullptr, nullptr,
                                      h, nullptr, n);

    // CSR build
    k_hist<<<(et + 255) / 256, 256>>>(ei, counts, E, n);
    k_scanA<<<nb, 1024>>>(counts, part, bsum, n);
    k_scanC<<<(n + 255) / 256, 256>>>(part, bsum, counts, rowptr, fillp, n);
    k_fill<<<(et + 255) / 256, 256>>>(ei, fillp, col, E, n);

    for (int l = 0; l < L; l++) {
        k_gemm_bf<<<tg, 256, GEMM_SMEM>>>(h, whi + (long)(l + 1) * HH * HH,
                                          wlo + (long)(l + 1) * HH * HH, nullptr,
                                          a_src + l * HH, a_dst + l * HH,
                                          asp, nullptr, hp16, n);
        k_combine<<<(n + 255) / 256, 256>>>(asp, asum, n);
        k_aggregate<<<(n * 32 + 255) / 256, 256>>>(rowptr, col, asum, ev, hp16,
                                                   bl + l * HH, h, n,
                                                   (l < L - 1) ? 1 : 0);
    }

    k_zero<<<(GG * HH / 4 + 255) / 256, 256>>>((float4*)pool, GG * HH / 4);
    k_pool<<<64, 256>>>(h, batch, pool, n);
    k_final<<<(GG * OO + 255) / 256, 256>>>(pool, Wf, bf, out);
}